// round 1
// baseline (speedup 1.0000x reference)
#include <cuda_runtime.h>
#include <cstdint>
#include <math.h>

// ---------------------------------------------------------------------------
// Problem constants
// ---------------------------------------------------------------------------
#define BATCH   8
#define DIMC    512
#define SPATIAL 1024           // H*W = 32*32
#define NTOK    (BATCH*SPATIAL)  // 8192 tokens
#define HEADS   8
#define HDIM    64
#define KVLEN   77
#define KVDIM   1024

// ---------------------------------------------------------------------------
// Scratch buffers (static device globals: allocation-free)
// ---------------------------------------------------------------------------
__device__ float g_x [(size_t)NTOK * DIMC];          // running activation
__device__ float g_t [(size_t)NTOK * DIMC];          // temp / normalized
__device__ float g_q [(size_t)NTOK * DIMC];
__device__ float g_k [(size_t)NTOK * DIMC];
__device__ float g_v [(size_t)NTOK * DIMC];
__device__ float g_s [(size_t)64 * 1024 * 1024];     // attention scores scratch
__device__ float g_h [(size_t)NTOK * 4096];          // FFN hidden
__device__ float g_gl[(size_t)NTOK * 2048];          // geglu output

// ---------------------------------------------------------------------------
// Warp reduction helpers
// ---------------------------------------------------------------------------
__device__ __forceinline__ float warpSum(float v) {
    #pragma unroll
    for (int o = 16; o > 0; o >>= 1) v += __shfl_xor_sync(0xffffffffu, v, o);
    return v;
}
__device__ __forceinline__ float warpMax(float v) {
    #pragma unroll
    for (int o = 16; o > 0; o >>= 1) v = fmaxf(v, __shfl_xor_sync(0xffffffffu, v, o));
    return v;
}

// ---------------------------------------------------------------------------
// GroupNorm (32 groups of 16 channels over 1024 spatial) + transpose to
// token-major [b*1024 + s, c].  One block per (batch, group).
// ---------------------------------------------------------------------------
__global__ void groupnorm_kernel(const float* __restrict__ qin,
                                 const float* __restrict__ gamma,
                                 const float* __restrict__ beta,
                                 float* __restrict__ out) {
    const int blk = blockIdx.x;
    const int b = blk >> 5;
    const int grp = blk & 31;
    const float* base = qin + ((size_t)b * DIMC + grp * 16) * SPATIAL;

    float s = 0.f, s2 = 0.f;
    for (int i = threadIdx.x; i < 16 * SPATIAL; i += 256) {
        float v = base[i];
        s += v; s2 += v * v;
    }
    __shared__ float red[2][8];
    s = warpSum(s); s2 = warpSum(s2);
    int wid = threadIdx.x >> 5, lid = threadIdx.x & 31;
    if (lid == 0) { red[0][wid] = s; red[1][wid] = s2; }
    __syncthreads();
    if (wid == 0) {
        float a = (lid < 8) ? red[0][lid] : 0.f;
        float c = (lid < 8) ? red[1][lid] : 0.f;
        a = warpSum(a); c = warpSum(c);
        if (lid == 0) { red[0][0] = a; red[1][0] = c; }
    }
    __syncthreads();
    const float mu  = red[0][0] * (1.f / 16384.f);
    const float var = red[1][0] * (1.f / 16384.f) - mu * mu;
    const float inv = rsqrtf(var + 1e-6f);

    for (int i = threadIdx.x; i < 16 * SPATIAL; i += 256) {
        int c = grp * 16 + (i >> 10);
        int sp = i & 1023;
        float v = (base[i] - mu) * inv * gamma[c] + beta[c];
        out[((size_t)(b * SPATIAL + sp)) * DIMC + c] = v;
    }
}

// ---------------------------------------------------------------------------
// LayerNorm over 512-dim rows. One warp per row.
// ---------------------------------------------------------------------------
__global__ void layernorm_kernel(const float* __restrict__ x,
                                 const float* __restrict__ gamma,
                                 const float* __restrict__ beta,
                                 float* __restrict__ out, int rows) {
    int row = blockIdx.x * 8 + (threadIdx.x >> 5);
    if (row >= rows) return;
    int lid = threadIdx.x & 31;
    const float4* xr = (const float4*)(x + (size_t)row * DIMC);

    float4 vals[4];
    float s = 0.f, s2 = 0.f;
    #pragma unroll
    for (int i = 0; i < 4; i++) {
        float4 v = xr[lid + 32 * i];
        vals[i] = v;
        s  += v.x + v.y + v.z + v.w;
        s2 += v.x*v.x + v.y*v.y + v.z*v.z + v.w*v.w;
    }
    s = warpSum(s); s2 = warpSum(s2);
    const float mu  = s * (1.f / 512.f);
    const float inv = rsqrtf(s2 * (1.f / 512.f) - mu * mu + 1e-5f);

    float4* orow = (float4*)(out + (size_t)row * DIMC);
    const float4* g4 = (const float4*)gamma;
    const float4* b4 = (const float4*)beta;
    #pragma unroll
    for (int i = 0; i < 4; i++) {
        int idx = lid + 32 * i;
        float4 v = vals[i], g = g4[idx], b = b4[idx], o;
        o.x = (v.x - mu) * inv * g.x + b.x;
        o.y = (v.y - mu) * inv * g.y + b.y;
        o.z = (v.z - mu) * inv * g.z + b.z;
        o.w = (v.w - mu) * inv * g.w + b.w;
        orow[idx] = o;
    }
}

// ---------------------------------------------------------------------------
// Row softmax (in place). One warp per row; row length L, leading dim ld.
// ---------------------------------------------------------------------------
__global__ void softmax_kernel(float* __restrict__ S, int rows, int L, int ld) {
    int row = blockIdx.x * 8 + (threadIdx.x >> 5);
    if (row >= rows) return;
    int lid = threadIdx.x & 31;
    float* p = S + (size_t)row * ld;

    float mx = -1e30f;
    for (int i = lid; i < L; i += 32) mx = fmaxf(mx, p[i]);
    mx = warpMax(mx);

    float sum = 0.f;
    for (int i = lid; i < L; i += 32) {
        float e = __expf(p[i] - mx);
        p[i] = e;
        sum += e;
    }
    sum = warpSum(sum);
    const float r = 1.f / sum;
    for (int i = lid; i < L; i += 32) p[i] *= r;
}

// ---------------------------------------------------------------------------
// GEGLU: out[r, j] = h[r, j] * gelu_exact(h[r, 2048 + j]), j < 2048
// ---------------------------------------------------------------------------
__global__ void geglu_kernel(const float* __restrict__ h,
                             float* __restrict__ out, int n) {
    int i = blockIdx.x * 256 + threadIdx.x;
    if (i >= n) return;
    size_t r = (size_t)(i >> 11);
    int c = i & 2047;
    float a = h[r * 4096 + c];
    float x = h[r * 4096 + 2048 + c];
    float ge = 0.5f * x * (1.f + erff(x * 0.70710678118654752f));
    out[i] = a * ge;
}

// ---------------------------------------------------------------------------
// Final transpose back to [B, C, H, W] + residual add with original q
// ---------------------------------------------------------------------------
__global__ void output_kernel(const float* __restrict__ t,
                              const float* __restrict__ qin,
                              float* __restrict__ out) {
    int i = blockIdx.x * 256 + threadIdx.x;
    if (i >= BATCH * DIMC * SPATIAL) return;
    int sp = i & 1023;
    int bc = i >> 10;
    int c = bc & 511;
    int b = bc >> 9;
    out[i] = t[((size_t)(b * SPATIAL + sp)) * DIMC + c] + qin[i];
}

// ---------------------------------------------------------------------------
// Generic batched tiled fp32 GEMM:
//   C = alpha * A @ B (+ bias) (+ Res),   A: [M,K] row-major (lda)
//   transB = 0: B[k,n] = B[k*ldb + n]   (row-major [K,N])
//   transB = 1: B[k,n] = B[n*ldb + k]   (i.e. C = A @ B^T of a [N,K] matrix)
// Batch offset for z: (z/zdiv)*strideOuter + (z%zdiv)*strideInner
// Block tile 128x128, K-step 16, 256 threads, 8x8 per-thread micro-tile.
// ---------------------------------------------------------------------------
__global__ void __launch_bounds__(256) gemm_kernel(
    const float* __restrict__ A, int lda, long long sAo, long long sAi,
    const float* __restrict__ B, int ldb, long long sBo, long long sBi,
    float* __restrict__ C, int ldc, long long sCo, long long sCi,
    const float* __restrict__ Res, int ldres,
    const float* __restrict__ bias,
    int M, int N, int K, float alpha, int transB, int zdiv) {

    const int z  = blockIdx.z;
    const int zo = z / zdiv, zi = z % zdiv;
    A += zo * sAo + zi * sAi;
    B += zo * sBo + zi * sBi;
    C += zo * sCo + zi * sCi;

    const int m0 = blockIdx.y * 128;
    const int n0 = blockIdx.x * 128;
    const int tid = threadIdx.x;
    const int ty = tid >> 4, tx = tid & 15;

    __shared__ float As[16][128];
    __shared__ float Bs[16][128];

    float acc[8][8];
    #pragma unroll
    for (int i = 0; i < 8; i++)
        #pragma unroll
        for (int j = 0; j < 8; j++) acc[i][j] = 0.f;

    for (int k0 = 0; k0 < K; k0 += 16) {
        // ---- load A tile (64x16 per pass, transposed into As[k][m]) ----
        {
            const int am = tid >> 2;
            const int ak = (tid & 3) * 4;
            #pragma unroll
            for (int r = 0; r < 128; r += 64) {
                const int mm = m0 + am + r;
                float4 va = make_float4(0.f, 0.f, 0.f, 0.f);
                if (mm < M) {
                    const int kk = k0 + ak;
                    if (kk + 3 < K) {
                        va = *(const float4*)(A + (long long)mm * lda + kk);
                    } else {
                        float tmp[4] = {0.f, 0.f, 0.f, 0.f};
                        #pragma unroll
                        for (int i = 0; i < 4; i++)
                            if (kk + i < K) tmp[i] = A[(long long)mm * lda + kk + i];
                        va = make_float4(tmp[0], tmp[1], tmp[2], tmp[3]);
                    }
                }
                As[ak + 0][am + r] = va.x;
                As[ak + 1][am + r] = va.y;
                As[ak + 2][am + r] = va.z;
                As[ak + 3][am + r] = va.w;
            }
        }
        // ---- load B tile ----
        if (!transB) {
            const int bk = tid >> 5;
            const int bn = (tid & 31) * 4;
            #pragma unroll
            for (int r = 0; r < 16; r += 8) {
                const int kk = k0 + bk + r;
                const int nn = n0 + bn;
                float4 vb = make_float4(0.f, 0.f, 0.f, 0.f);
                if (kk < K) {
                    if (nn + 3 < N) {
                        vb = *(const float4*)(B + (long long)kk * ldb + nn);
                    } else {
                        float tmp[4] = {0.f, 0.f, 0.f, 0.f};
                        #pragma unroll
                        for (int i = 0; i < 4; i++)
                            if (nn + i < N) tmp[i] = B[(long long)kk * ldb + nn + i];
                        vb = make_float4(tmp[0], tmp[1], tmp[2], tmp[3]);
                    }
                }
                *(float4*)&Bs[bk + r][bn] = vb;
            }
        } else {
            const int bn = tid >> 2;
            const int bk = (tid & 3) * 4;
            #pragma unroll
            for (int r = 0; r < 128; r += 64) {
                const int nn = n0 + bn + r;
                float4 vb = make_float4(0.f, 0.f, 0.f, 0.f);
                if (nn < N) {
                    const int kk = k0 + bk;
                    if (kk + 3 < K) {
                        vb = *(const float4*)(B + (long long)nn * ldb + kk);
                    } else {
                        float tmp[4] = {0.f, 0.f, 0.f, 0.f};
                        #pragma unroll
                        for (int i = 0; i < 4; i++)
                            if (kk + i < K) tmp[i] = B[(long long)nn * ldb + kk + i];
                        vb = make_float4(tmp[0], tmp[1], tmp[2], tmp[3]);
                    }
                }
                Bs[bk + 0][bn + r] = vb.x;
                Bs[bk + 1][bn + r] = vb.y;
                Bs[bk + 2][bn + r] = vb.z;
                Bs[bk + 3][bn + r] = vb.w;
            }
        }
        __syncthreads();

        #pragma unroll
        for (int k = 0; k < 16; k++) {
            float a[8], b[8];
            *(float4*)&a[0] = *(const float4*)&As[k][ty * 8];
            *(float4*)&a[4] = *(const float4*)&As[k][ty * 8 + 4];
            *(float4*)&b[0] = *(const float4*)&Bs[k][tx * 8];
            *(float4*)&b[4] = *(const float4*)&Bs[k][tx * 8 + 4];
            #pragma unroll
            for (int i = 0; i < 8; i++)
                #pragma unroll
                for (int j = 0; j < 8; j++)
                    acc[i][j] += a[i] * b[j];
        }
        __syncthreads();
    }

    // ---- epilogue ----
    #pragma unroll
    for (int i = 0; i < 8; i++) {
        const int row = m0 + ty * 8 + i;
        if (row >= M) continue;
        #pragma unroll
        for (int j = 0; j < 8; j++) {
            const int col = n0 + tx * 8 + j;
            if (col >= N) continue;
            float v = acc[i][j] * alpha;
            if (bias) v += bias[col];
            if (Res) v += Res[(long long)row * ldres + col];
            C[(long long)row * ldc + col] = v;
        }
    }
}

// ---------------------------------------------------------------------------
// Host side
// ---------------------------------------------------------------------------
static void gemm(const float* A, int lda, long long sAo, long long sAi,
                 const float* B, int ldb, long long sBo, long long sBi,
                 float* C, int ldc, long long sCo, long long sCi,
                 const float* Res, int ldres, const float* bias,
                 int M, int N, int K, float alpha, int transB, int zdiv,
                 int batch) {
    dim3 grid((N + 127) / 128, (M + 127) / 128, batch);
    gemm_kernel<<<grid, 256>>>(A, lda, sAo, sAi, B, ldb, sBo, sBi,
                               C, ldc, sCo, sCi, Res, ldres, bias,
                               M, N, K, alpha, transB, zdiv);
}

extern "C" void kernel_launch(void* const* d_in, const int* in_sizes, int n_in,
                              void* d_out, int out_size) {
    const float* in_q     = (const float*)d_in[0];
    const float* in_kv    = (const float*)d_in[1];
    const float* gn_g     = (const float*)d_in[2];
    const float* gn_b     = (const float*)d_in[3];
    const float* ln2_g    = (const float*)d_in[4];
    const float* ln2_b    = (const float*)d_in[5];
    const float* ln3_g    = (const float*)d_in[6];
    const float* ln3_b    = (const float*)d_in[7];
    const float* ln4_g    = (const float*)d_in[8];
    const float* ln4_b    = (const float*)d_in[9];
    const float* fc_in_w  = (const float*)d_in[10];
    const float* fc_in_b  = (const float*)d_in[11];
    const float* fc_out_w = (const float*)d_in[12];
    const float* fc_out_b = (const float*)d_in[13];
    const float* a1_q     = (const float*)d_in[14];
    const float* a1_k     = (const float*)d_in[15];
    const float* a1_v     = (const float*)d_in[16];
    const float* a1_o     = (const float*)d_in[17];
    const float* a1_ob    = (const float*)d_in[18];
    const float* a2_q     = (const float*)d_in[19];
    const float* a2_k     = (const float*)d_in[20];
    const float* a2_v     = (const float*)d_in[21];
    const float* a2_o     = (const float*)d_in[22];
    const float* a2_ob    = (const float*)d_in[23];
    const float* ff_proj_w = (const float*)d_in[24];
    const float* ff_proj_b = (const float*)d_in[25];
    const float* ff_out_w  = (const float*)d_in[26];
    const float* ff_out_b  = (const float*)d_in[27];

    float *x, *t, *q, *k, *v, *s, *h, *gl;
    cudaGetSymbolAddress((void**)&x,  g_x);
    cudaGetSymbolAddress((void**)&t,  g_t);
    cudaGetSymbolAddress((void**)&q,  g_q);
    cudaGetSymbolAddress((void**)&k,  g_k);
    cudaGetSymbolAddress((void**)&v,  g_v);
    cudaGetSymbolAddress((void**)&s,  g_s);
    cudaGetSymbolAddress((void**)&h,  g_h);
    cudaGetSymbolAddress((void**)&gl, g_gl);

    float* out = (float*)d_out;

    // 1. GroupNorm + transpose to tokens -> t
    groupnorm_kernel<<<BATCH * 32, 256>>>(in_q, gn_g, gn_b, t);

    // 2. x = t @ fc_in_w + fc_in_b
    gemm(t, 512, 0, 0, fc_in_w, 512, 0, 0, x, 512, 0, 0,
         nullptr, 0, fc_in_b, NTOK, 512, 512, 1.f, 0, 1, 1);

    // ---- self attention ----
    // 3. t = LN(x; ln2)
    layernorm_kernel<<<NTOK / 8, 256>>>(x, ln2_g, ln2_b, t, NTOK);
    // 4-6. q/k/v projections
    gemm(t, 512, 0, 0, a1_q, 512, 0, 0, q, 512, 0, 0, nullptr, 0, nullptr,
         NTOK, 512, 512, 1.f, 0, 1, 1);
    gemm(t, 512, 0, 0, a1_k, 512, 0, 0, k, 512, 0, 0, nullptr, 0, nullptr,
         NTOK, 512, 512, 1.f, 0, 1, 1);
    gemm(t, 512, 0, 0, a1_v, 512, 0, 0, v, 512, 0, 0, nullptr, 0, nullptr,
         NTOK, 512, 512, 1.f, 0, 1, 1);
    // 7. S[b,h] = Qh @ Kh^T * 1/8   (z = b*8+h)
    gemm(q, 512, 524288, 64, k, 512, 524288, 64,
         s, 1024, 8388608, 1048576, nullptr, 0, nullptr,
         1024, 1024, 64, 0.125f, 1, 8, 64);
    // 8. softmax
    softmax_kernel<<<(64 * 1024) / 8, 256>>>(s, 64 * 1024, 1024, 1024);
    // 9. O = S @ Vh  -> t  (heads packed back into 512 cols)
    gemm(s, 1024, 8388608, 1048576, v, 512, 524288, 64,
         t, 512, 524288, 64, nullptr, 0, nullptr,
         1024, 64, 1024, 1.f, 0, 8, 64);
    // 10. x = t @ a1_o + a1_ob + x
    gemm(t, 512, 0, 0, a1_o, 512, 0, 0, x, 512, 0, 0,
         x, 512, a1_ob, NTOK, 512, 512, 1.f, 0, 1, 1);

    // ---- cross attention ----
    // 11. t = LN(x; ln3)
    layernorm_kernel<<<NTOK / 8, 256>>>(x, ln3_g, ln3_b, t, NTOK);
    // 12. q = t @ a2_q
    gemm(t, 512, 0, 0, a2_q, 512, 0, 0, q, 512, 0, 0, nullptr, 0, nullptr,
         NTOK, 512, 512, 1.f, 0, 1, 1);
    // 13-14. k/v from kv  (616 rows = 8*77, K = 1024)
    gemm(in_kv, 1024, 0, 0, a2_k, 512, 0, 0, k, 512, 0, 0, nullptr, 0, nullptr,
         BATCH * KVLEN, 512, 1024, 1.f, 0, 1, 1);
    gemm(in_kv, 1024, 0, 0, a2_v, 512, 0, 0, v, 512, 0, 0, nullptr, 0, nullptr,
         BATCH * KVLEN, 512, 1024, 1.f, 0, 1, 1);
    // 15. S = Qh @ Kh^T * 1/8, N = 77, ldc = 128 (padded)
    gemm(q, 512, 524288, 64, k, 512, (long long)KVLEN * 512, 64,
         s, 128, 1048576, 131072, nullptr, 0, nullptr,
         1024, KVLEN, 64, 0.125f, 1, 8, 64);
    // 16. softmax (L = 77, ld = 128)
    softmax_kernel<<<(64 * 1024) / 8, 256>>>(s, 64 * 1024, KVLEN, 128);
    // 17. O = S @ Vh -> t
    gemm(s, 128, 1048576, 131072, v, 512, (long long)KVLEN * 512, 64,
         t, 512, 524288, 64, nullptr, 0, nullptr,
         1024, 64, KVLEN, 1.f, 0, 8, 64);
    // 18. x = t @ a2_o + a2_ob + x
    gemm(t, 512, 0, 0, a2_o, 512, 0, 0, x, 512, 0, 0,
         x, 512, a2_ob, NTOK, 512, 512, 1.f, 0, 1, 1);

    // ---- feed-forward (GEGLU) ----
    // 19. t = LN(x; ln4)
    layernorm_kernel<<<NTOK / 8, 256>>>(x, ln4_g, ln4_b, t, NTOK);
    // 20. h = t @ ff_proj_w + ff_proj_b   (N = 4096)
    gemm(t, 512, 0, 0, ff_proj_w, 4096, 0, 0, h, 4096, 0, 0,
         nullptr, 0, ff_proj_b, NTOK, 4096, 512, 1.f, 0, 1, 1);
    // 21. geglu -> gl  (NTOK x 2048)
    geglu_kernel<<<(NTOK * 2048) / 256, 256>>>(h, gl, NTOK * 2048);
    // 22. x = gl @ ff_out_w + ff_out_b + x
    gemm(gl, 2048, 0, 0, ff_out_w, 512, 0, 0, x, 512, 0, 0,
         x, 512, ff_out_b, NTOK, 512, 2048, 1.f, 0, 1, 1);

    // 23. t = x @ fc_out_w + fc_out_b
    gemm(x, 512, 0, 0, fc_out_w, 512, 0, 0, t, 512, 0, 0,
         nullptr, 0, fc_out_b, NTOK, 512, 512, 1.f, 0, 1, 1);

    // 24. out = transpose(t) + original q residual
    output_kernel<<<(BATCH * DIMC * SPATIAL) / 256, 256>>>(t, in_q, out);
}

// round 2
// speedup vs baseline: 3.9586x; 3.9586x over previous
#include <cuda_runtime.h>
#include <cstdint>
#include <math.h>

// ---------------------------------------------------------------------------
// Problem constants
// ---------------------------------------------------------------------------
#define BATCH   8
#define DIMC    512
#define SPATIAL 1024             // H*W = 32*32
#define NTOK    (BATCH*SPATIAL)  // 8192 tokens
#define HEADS   8
#define HDIM    64
#define KVLEN   77
#define KVDIM   1024

// ---------------------------------------------------------------------------
// Scratch buffers (static device globals: allocation-free)
// ---------------------------------------------------------------------------
__device__ float g_x [(size_t)NTOK * DIMC];          // running activation
__device__ float g_t [(size_t)NTOK * DIMC];          // temp / normalized
__device__ float g_q [(size_t)NTOK * DIMC];
__device__ float g_k [(size_t)NTOK * DIMC];
__device__ float g_v [(size_t)NTOK * DIMC];
__device__ float g_s [(size_t)64 * 1024 * 1024];     // attention scores scratch
__device__ float g_h [(size_t)NTOK * 4096];          // FFN hidden
__device__ float g_gl[(size_t)NTOK * 2048];          // geglu output

// ---------------------------------------------------------------------------
// Warp reduction helpers
// ---------------------------------------------------------------------------
__device__ __forceinline__ float warpSum(float v) {
    #pragma unroll
    for (int o = 16; o > 0; o >>= 1) v += __shfl_xor_sync(0xffffffffu, v, o);
    return v;
}
__device__ __forceinline__ float warpMax(float v) {
    #pragma unroll
    for (int o = 16; o > 0; o >>= 1) v = fmaxf(v, __shfl_xor_sync(0xffffffffu, v, o));
    return v;
}

// ---------------------------------------------------------------------------
// GroupNorm + transpose to token-major
// ---------------------------------------------------------------------------
__global__ void groupnorm_kernel(const float* __restrict__ qin,
                                 const float* __restrict__ gamma,
                                 const float* __restrict__ beta,
                                 float* __restrict__ out) {
    const int blk = blockIdx.x;
    const int b = blk >> 5;
    const int grp = blk & 31;
    const float* base = qin + ((size_t)b * DIMC + grp * 16) * SPATIAL;

    float s = 0.f, s2 = 0.f;
    for (int i = threadIdx.x; i < 16 * SPATIAL; i += 256) {
        float v = base[i];
        s += v; s2 += v * v;
    }
    __shared__ float red[2][8];
    s = warpSum(s); s2 = warpSum(s2);
    int wid = threadIdx.x >> 5, lid = threadIdx.x & 31;
    if (lid == 0) { red[0][wid] = s; red[1][wid] = s2; }
    __syncthreads();
    if (wid == 0) {
        float a = (lid < 8) ? red[0][lid] : 0.f;
        float c = (lid < 8) ? red[1][lid] : 0.f;
        a = warpSum(a); c = warpSum(c);
        if (lid == 0) { red[0][0] = a; red[1][0] = c; }
    }
    __syncthreads();
    const float mu  = red[0][0] * (1.f / 16384.f);
    const float var = red[1][0] * (1.f / 16384.f) - mu * mu;
    const float inv = rsqrtf(var + 1e-6f);

    for (int i = threadIdx.x; i < 16 * SPATIAL; i += 256) {
        int c = grp * 16 + (i >> 10);
        int sp = i & 1023;
        float v = (base[i] - mu) * inv * gamma[c] + beta[c];
        out[((size_t)(b * SPATIAL + sp)) * DIMC + c] = v;
    }
}

// ---------------------------------------------------------------------------
// LayerNorm over 512-dim rows. One warp per row.
// ---------------------------------------------------------------------------
__global__ void layernorm_kernel(const float* __restrict__ x,
                                 const float* __restrict__ gamma,
                                 const float* __restrict__ beta,
                                 float* __restrict__ out, int rows) {
    int row = blockIdx.x * 8 + (threadIdx.x >> 5);
    if (row >= rows) return;
    int lid = threadIdx.x & 31;
    const float4* xr = (const float4*)(x + (size_t)row * DIMC);

    float4 vals[4];
    float s = 0.f, s2 = 0.f;
    #pragma unroll
    for (int i = 0; i < 4; i++) {
        float4 v = xr[lid + 32 * i];
        vals[i] = v;
        s  += v.x + v.y + v.z + v.w;
        s2 += v.x*v.x + v.y*v.y + v.z*v.z + v.w*v.w;
    }
    s = warpSum(s); s2 = warpSum(s2);
    const float mu  = s * (1.f / 512.f);
    const float inv = rsqrtf(s2 * (1.f / 512.f) - mu * mu + 1e-5f);

    float4* orow = (float4*)(out + (size_t)row * DIMC);
    const float4* g4 = (const float4*)gamma;
    const float4* b4 = (const float4*)beta;
    #pragma unroll
    for (int i = 0; i < 4; i++) {
        int idx = lid + 32 * i;
        float4 v = vals[i], g = g4[idx], b = b4[idx], o;
        o.x = (v.x - mu) * inv * g.x + b.x;
        o.y = (v.y - mu) * inv * g.y + b.y;
        o.z = (v.z - mu) * inv * g.z + b.z;
        o.w = (v.w - mu) * inv * g.w + b.w;
        orow[idx] = o;
    }
}

// ---------------------------------------------------------------------------
// Row softmax (in place). One warp per row.
// ---------------------------------------------------------------------------
__global__ void softmax_kernel(float* __restrict__ S, int rows, int L, int ld) {
    int row = blockIdx.x * 8 + (threadIdx.x >> 5);
    if (row >= rows) return;
    int lid = threadIdx.x & 31;
    float* p = S + (size_t)row * ld;

    float mx = -1e30f;
    for (int i = lid; i < L; i += 32) mx = fmaxf(mx, p[i]);
    mx = warpMax(mx);

    float sum = 0.f;
    for (int i = lid; i < L; i += 32) {
        float e = __expf(p[i] - mx);
        p[i] = e;
        sum += e;
    }
    sum = warpSum(sum);
    const float r = 1.f / sum;
    for (int i = lid; i < L; i += 32) p[i] *= r;
}

// ---------------------------------------------------------------------------
// GEGLU
// ---------------------------------------------------------------------------
__global__ void geglu_kernel(const float* __restrict__ h,
                             float* __restrict__ out, int n) {
    int i = blockIdx.x * 256 + threadIdx.x;
    if (i >= n) return;
    size_t r = (size_t)(i >> 11);
    int c = i & 2047;
    float a = h[r * 4096 + c];
    float x = h[r * 4096 + 2048 + c];
    float ge = 0.5f * x * (1.f + erff(x * 0.70710678118654752f));
    out[i] = a * ge;
}

// ---------------------------------------------------------------------------
// Final transpose + residual
// ---------------------------------------------------------------------------
__global__ void output_kernel(const float* __restrict__ t,
                              const float* __restrict__ qin,
                              float* __restrict__ out) {
    int i = blockIdx.x * 256 + threadIdx.x;
    if (i >= BATCH * DIMC * SPATIAL) return;
    int sp = i & 1023;
    int bc = i >> 10;
    int c = bc & 511;
    int b = bc >> 9;
    out[i] = t[((size_t)(b * SPATIAL + sp)) * DIMC + c] + qin[i];
}

// ===========================================================================
// TF32 tensor-core GEMM
//   C = alpha * A @ op(B) (+ bias) (+ Res)
//   A: [M,K] row-major. transB=0: B row-major [K,N]. transB=1: B [N,K].
//   Batched via blockIdx.z with (outer, inner) strides, z = zo*zdiv + zi.
//   128x128x32 tile, 256 threads (8 warps, 2x4), m16n8k8 mma, cp.async
//   double buffering, zero-fill for all M/N/K edges.
// ===========================================================================
#define BM 128
#define BN 128
#define BK 32
// per-stage smem: As 128x36 floats (pad 4), Bs 4608 floats
//   transB=0: Bs[k][136]  (pad 8) ; transB=1: Bs[n][36] (pad 4)
#define STAGE_FLOATS 9216
#define SMEM_BYTES (2 * STAGE_FLOATS * 4)

__device__ __forceinline__ void cp_async16(uint32_t dst, const void* src, int bytes) {
    asm volatile("cp.async.cg.shared.global [%0], [%1], 16, %2;\n"
                 :: "r"(dst), "l"(src), "r"(bytes));
}
__device__ __forceinline__ void cp_commit() {
    asm volatile("cp.async.commit_group;\n");
}
__device__ __forceinline__ void cp_wait_all() {
    asm volatile("cp.async.wait_group 0;\n");
}
__device__ __forceinline__ uint32_t f2tf32(float v) {
    uint32_t r;
    asm("cvt.rna.tf32.f32 %0, %1;" : "=r"(r) : "f"(v));
    return r;
}
__device__ __forceinline__ void mma_tf32(float* d, const uint32_t* a, const uint32_t* b) {
    asm volatile(
        "mma.sync.aligned.m16n8k8.row.col.f32.tf32.tf32.f32 "
        "{%0,%1,%2,%3}, {%4,%5,%6,%7}, {%8,%9}, {%0,%1,%2,%3};"
        : "+f"(d[0]), "+f"(d[1]), "+f"(d[2]), "+f"(d[3])
        : "r"(a[0]), "r"(a[1]), "r"(a[2]), "r"(a[3]), "r"(b[0]), "r"(b[1]));
}

__global__ void __launch_bounds__(256) gemm_tf32_kernel(
    const float* __restrict__ A, int lda, long long sAo, long long sAi,
    const float* __restrict__ B, int ldb, long long sBo, long long sBi,
    float* __restrict__ C, int ldc, long long sCo, long long sCi,
    const float* __restrict__ Res, int ldres,
    const float* __restrict__ bias,
    int M, int N, int K, float alpha, int transB, int zdiv) {

    extern __shared__ float smem[];

    const int z  = blockIdx.z;
    const int zo = z / zdiv, zi = z % zdiv;
    A += zo * sAo + zi * sAi;
    B += zo * sBo + zi * sBi;
    C += zo * sCo + zi * sCi;

    const int m0 = blockIdx.y * BM;
    const int n0 = blockIdx.x * BN;
    const int tid = threadIdx.x;
    const int warp = tid >> 5;
    const int lane = tid & 31;
    const int g  = lane >> 2;   // group id (0..7)
    const int tg = lane & 3;    // thread-in-group (0..3)
    const int wm = (warp >> 2) * 64;  // warp M offset within tile
    const int wn = (warp & 3) * 32;   // warp N offset within tile

    const uint32_t smem_u32 = (uint32_t)__cvta_generic_to_shared(smem);
    const int nk = (K + BK - 1) / BK;

    float acc[4][4][4];
    #pragma unroll
    for (int i = 0; i < 4; i++)
        #pragma unroll
        for (int j = 0; j < 4; j++)
            #pragma unroll
            for (int r = 0; r < 4; r++) acc[i][j][r] = 0.f;

    // ---- async load of one k-stage ----
    auto load_stage = [&](int stage, int k0) {
        const uint32_t abase = smem_u32 + (uint32_t)stage * STAGE_FLOATS * 4;
        // A tile: 128 rows x 32 floats = 1024 x 16B chunks / 256 thr = 4 each
        #pragma unroll
        for (int i = 0; i < 4; i++) {
            int idx = tid + i * 256;
            int row = idx >> 3;
            int kc  = (idx & 7) * 4;
            int bytes = 0;
            if (m0 + row < M) {
                int rem = K - (k0 + kc);
                bytes = rem >= 4 ? 16 : (rem > 0 ? rem * 4 : 0);
            }
            cp_async16(abase + (uint32_t)(row * 36 + kc) * 4,
                       A + (long long)(m0 + row) * lda + k0 + kc, bytes);
        }
        const uint32_t bbase = abase + 4608u * 4;
        if (!transB) {
            // B tile: 32 k-rows x 128 floats
            #pragma unroll
            for (int i = 0; i < 4; i++) {
                int idx = tid + i * 256;
                int k  = idx >> 5;
                int nc = (idx & 31) * 4;
                int bytes = 0;
                if (k0 + k < K) {
                    int rem = N - (n0 + nc);
                    bytes = rem >= 4 ? 16 : (rem > 0 ? rem * 4 : 0);
                }
                cp_async16(bbase + (uint32_t)(k * 136 + nc) * 4,
                           B + (long long)(k0 + k) * ldb + n0 + nc, bytes);
            }
        } else {
            // B^T tile: 128 n-rows x 32 floats
            #pragma unroll
            for (int i = 0; i < 4; i++) {
                int idx = tid + i * 256;
                int n  = idx >> 3;
                int kc = (idx & 7) * 4;
                int bytes = 0;
                if (n0 + n < N) {
                    int rem = K - (k0 + kc);
                    bytes = rem >= 4 ? 16 : (rem > 0 ? rem * 4 : 0);
                }
                cp_async16(bbase + (uint32_t)(n * 36 + kc) * 4,
                           B + (long long)(n0 + n) * ldb + k0 + kc, bytes);
            }
        }
        cp_commit();
    };

    // ---- compute one k-stage ----
    auto compute_stage = [&](int stage) {
        const float* As = smem + stage * STAGE_FLOATS;
        const float* Bs = As + 4608;
        #pragma unroll
        for (int ks = 0; ks < 4; ks++) {
            const int kk = ks * 8;
            uint32_t afr[4][4];
            #pragma unroll
            for (int mt = 0; mt < 4; mt++) {
                const int mb = wm + mt * 16;
                afr[mt][0] = f2tf32(As[(mb + g)     * 36 + kk + tg]);
                afr[mt][1] = f2tf32(As[(mb + g + 8) * 36 + kk + tg]);
                afr[mt][2] = f2tf32(As[(mb + g)     * 36 + kk + tg + 4]);
                afr[mt][3] = f2tf32(As[(mb + g + 8) * 36 + kk + tg + 4]);
            }
            uint32_t bfr[4][2];
            if (!transB) {
                #pragma unroll
                for (int nt = 0; nt < 4; nt++) {
                    const int nb = wn + nt * 8;
                    bfr[nt][0] = f2tf32(Bs[(kk + tg)     * 136 + nb + g]);
                    bfr[nt][1] = f2tf32(Bs[(kk + tg + 4) * 136 + nb + g]);
                }
            } else {
                #pragma unroll
                for (int nt = 0; nt < 4; nt++) {
                    const int nb = wn + nt * 8;
                    bfr[nt][0] = f2tf32(Bs[(nb + g) * 36 + kk + tg]);
                    bfr[nt][1] = f2tf32(Bs[(nb + g) * 36 + kk + tg + 4]);
                }
            }
            #pragma unroll
            for (int mt = 0; mt < 4; mt++)
                #pragma unroll
                for (int nt = 0; nt < 4; nt++)
                    mma_tf32(acc[mt][nt], afr[mt], bfr[nt]);
        }
    };

    load_stage(0, 0);
    for (int kt = 0; kt < nk; kt++) {
        cp_wait_all();
        __syncthreads();
        if (kt + 1 < nk) load_stage((kt + 1) & 1, (kt + 1) * BK);
        compute_stage(kt & 1);
        __syncthreads();
    }

    // ---- epilogue ----
    #pragma unroll
    for (int mt = 0; mt < 4; mt++) {
        #pragma unroll
        for (int nt = 0; nt < 4; nt++) {
            const int row0 = m0 + wm + mt * 16 + g;
            const int col0 = n0 + wn + nt * 8 + tg * 2;
            #pragma unroll
            for (int r = 0; r < 4; r++) {
                const int row = row0 + (r >> 1) * 8;
                const int col = col0 + (r & 1);
                if (row < M && col < N) {
                    float v = acc[mt][nt][r] * alpha;
                    if (bias) v += bias[col];
                    if (Res)  v += Res[(long long)row * ldres + col];
                    C[(long long)row * ldc + col] = v;
                }
            }
        }
    }
}

// ---------------------------------------------------------------------------
// Host side
// ---------------------------------------------------------------------------
static void gemm(const float* A, int lda, long long sAo, long long sAi,
                 const float* B, int ldb, long long sBo, long long sBi,
                 float* C, int ldc, long long sCo, long long sCi,
                 const float* Res, int ldres, const float* bias,
                 int M, int N, int K, float alpha, int transB, int zdiv,
                 int batch) {
    dim3 grid((N + BN - 1) / BN, (M + BM - 1) / BM, batch);
    gemm_tf32_kernel<<<grid, 256, SMEM_BYTES>>>(
        A, lda, sAo, sAi, B, ldb, sBo, sBi,
        C, ldc, sCo, sCi, Res, ldres, bias,
        M, N, K, alpha, transB, zdiv);
}

extern "C" void kernel_launch(void* const* d_in, const int* in_sizes, int n_in,
                              void* d_out, int out_size) {
    const float* in_q     = (const float*)d_in[0];
    const float* in_kv    = (const float*)d_in[1];
    const float* gn_g     = (const float*)d_in[2];
    const float* gn_b     = (const float*)d_in[3];
    const float* ln2_g    = (const float*)d_in[4];
    const float* ln2_b    = (const float*)d_in[5];
    const float* ln3_g    = (const float*)d_in[6];
    const float* ln3_b    = (const float*)d_in[7];
    const float* ln4_g    = (const float*)d_in[8];
    const float* ln4_b    = (const float*)d_in[9];
    const float* fc_in_w  = (const float*)d_in[10];
    const float* fc_in_b  = (const float*)d_in[11];
    const float* fc_out_w = (const float*)d_in[12];
    const float* fc_out_b = (const float*)d_in[13];
    const float* a1_q     = (const float*)d_in[14];
    const float* a1_k     = (const float*)d_in[15];
    const float* a1_v     = (const float*)d_in[16];
    const float* a1_o     = (const float*)d_in[17];
    const float* a1_ob    = (const float*)d_in[18];
    const float* a2_q     = (const float*)d_in[19];
    const float* a2_k     = (const float*)d_in[20];
    const float* a2_v     = (const float*)d_in[21];
    const float* a2_o     = (const float*)d_in[22];
    const float* a2_ob    = (const float*)d_in[23];
    const float* ff_proj_w = (const float*)d_in[24];
    const float* ff_proj_b = (const float*)d_in[25];
    const float* ff_out_w  = (const float*)d_in[26];
    const float* ff_out_b  = (const float*)d_in[27];

    // allow >48KB dynamic smem (host-side attribute, idempotent)
    cudaFuncSetAttribute(gemm_tf32_kernel,
                         cudaFuncAttributeMaxDynamicSharedMemorySize, SMEM_BYTES);

    float *x, *t, *q, *k, *v, *s, *h, *gl;
    cudaGetSymbolAddress((void**)&x,  g_x);
    cudaGetSymbolAddress((void**)&t,  g_t);
    cudaGetSymbolAddress((void**)&q,  g_q);
    cudaGetSymbolAddress((void**)&k,  g_k);
    cudaGetSymbolAddress((void**)&v,  g_v);
    cudaGetSymbolAddress((void**)&s,  g_s);
    cudaGetSymbolAddress((void**)&h,  g_h);
    cudaGetSymbolAddress((void**)&gl, g_gl);

    float* out = (float*)d_out;

    // 1. GroupNorm + transpose to tokens -> t
    groupnorm_kernel<<<BATCH * 32, 256>>>(in_q, gn_g, gn_b, t);

    // 2. x = t @ fc_in_w + fc_in_b
    gemm(t, 512, 0, 0, fc_in_w, 512, 0, 0, x, 512, 0, 0,
         nullptr, 0, fc_in_b, NTOK, 512, 512, 1.f, 0, 1, 1);

    // ---- self attention ----
    layernorm_kernel<<<NTOK / 8, 256>>>(x, ln2_g, ln2_b, t, NTOK);
    gemm(t, 512, 0, 0, a1_q, 512, 0, 0, q, 512, 0, 0, nullptr, 0, nullptr,
         NTOK, 512, 512, 1.f, 0, 1, 1);
    gemm(t, 512, 0, 0, a1_k, 512, 0, 0, k, 512, 0, 0, nullptr, 0, nullptr,
         NTOK, 512, 512, 1.f, 0, 1, 1);
    gemm(t, 512, 0, 0, a1_v, 512, 0, 0, v, 512, 0, 0, nullptr, 0, nullptr,
         NTOK, 512, 512, 1.f, 0, 1, 1);
    // S[b,h] = Qh @ Kh^T * 1/8   (z = b*8+h)
    gemm(q, 512, 524288, 64, k, 512, 524288, 64,
         s, 1024, 8388608, 1048576, nullptr, 0, nullptr,
         1024, 1024, 64, 0.125f, 1, 8, 64);
    softmax_kernel<<<(64 * 1024) / 8, 256>>>(s, 64 * 1024, 1024, 1024);
    // O = S @ Vh
    gemm(s, 1024, 8388608, 1048576, v, 512, 524288, 64,
         t, 512, 524288, 64, nullptr, 0, nullptr,
         1024, 64, 1024, 1.f, 0, 8, 64);
    gemm(t, 512, 0, 0, a1_o, 512, 0, 0, x, 512, 0, 0,
         x, 512, a1_ob, NTOK, 512, 512, 1.f, 0, 1, 1);

    // ---- cross attention ----
    layernorm_kernel<<<NTOK / 8, 256>>>(x, ln3_g, ln3_b, t, NTOK);
    gemm(t, 512, 0, 0, a2_q, 512, 0, 0, q, 512, 0, 0, nullptr, 0, nullptr,
         NTOK, 512, 512, 1.f, 0, 1, 1);
    gemm(in_kv, 1024, 0, 0, a2_k, 512, 0, 0, k, 512, 0, 0, nullptr, 0, nullptr,
         BATCH * KVLEN, 512, 1024, 1.f, 0, 1, 1);
    gemm(in_kv, 1024, 0, 0, a2_v, 512, 0, 0, v, 512, 0, 0, nullptr, 0, nullptr,
         BATCH * KVLEN, 512, 1024, 1.f, 0, 1, 1);
    // S = Qh @ Kh^T * 1/8, N = 77, ldc = 128 (padded)
    gemm(q, 512, 524288, 64, k, 512, (long long)KVLEN * 512, 64,
         s, 128, 1048576, 131072, nullptr, 0, nullptr,
         1024, KVLEN, 64, 0.125f, 1, 8, 64);
    softmax_kernel<<<(64 * 1024) / 8, 256>>>(s, 64 * 1024, KVLEN, 128);
    gemm(s, 128, 1048576, 131072, v, 512, (long long)KVLEN * 512, 64,
         t, 512, 524288, 64, nullptr, 0, nullptr,
         1024, 64, KVLEN, 1.f, 0, 8, 64);
    gemm(t, 512, 0, 0, a2_o, 512, 0, 0, x, 512, 0, 0,
         x, 512, a2_ob, NTOK, 512, 512, 1.f, 0, 1, 1);

    // ---- feed-forward (GEGLU) ----
    layernorm_kernel<<<NTOK / 8, 256>>>(x, ln4_g, ln4_b, t, NTOK);
    gemm(t, 512, 0, 0, ff_proj_w, 4096, 0, 0, h, 4096, 0, 0,
         nullptr, 0, ff_proj_b, NTOK, 4096, 512, 1.f, 0, 1, 1);
    geglu_kernel<<<(NTOK * 2048) / 256, 256>>>(h, gl, NTOK * 2048);
    gemm(gl, 2048, 0, 0, ff_out_w, 512, 0, 0, x, 512, 0, 0,
         x, 512, ff_out_b, NTOK, 512, 2048, 1.f, 0, 1, 1);

    // ---- output projection ----
    gemm(x, 512, 0, 0, fc_out_w, 512, 0, 0, t, 512, 0, 0,
         nullptr, 0, fc_out_b, NTOK, 512, 512, 1.f, 0, 1, 1);

    output_kernel<<<(BATCH * DIMC * SPATIAL) / 256, 256>>>(t, in_q, out);
}

// round 3
// speedup vs baseline: 4.5337x; 1.1453x over previous
#include <cuda_runtime.h>
#include <cstdint>
#include <math.h>

// ---------------------------------------------------------------------------
// Problem constants
// ---------------------------------------------------------------------------
#define BATCH   8
#define DIMC    512
#define SPATIAL 1024             // H*W = 32*32
#define NTOK    (BATCH*SPATIAL)  // 8192 tokens
#define HEADS   8
#define HDIM    64
#define KVLEN   77
#define KVDIM   1024

// ---------------------------------------------------------------------------
// Scratch buffers (static device globals: allocation-free)
// ---------------------------------------------------------------------------
__device__ float g_x   [(size_t)NTOK * DIMC];        // running activation
__device__ float g_t   [(size_t)NTOK * DIMC];        // temp / normalized
__device__ float g_q   [(size_t)NTOK * DIMC];        // cross-attn q
__device__ float g_qkv [(size_t)NTOK * 1536];        // packed self-attn q|k|v
__device__ float g_kv2 [(size_t)(BATCH*KVLEN) * 1024]; // packed cross k|v
__device__ float g_wq  [(size_t)512 * 1536];         // packed qkv weights
__device__ float g_wk2 [(size_t)1024 * 1024];        // packed cross kv weights
__device__ float g_s   [(size_t)64 * 1024 * 1024];   // attention scores scratch
__device__ float g_gl  [(size_t)NTOK * 2048];        // geglu a-half / output

// ---------------------------------------------------------------------------
// Warp reduction helpers
// ---------------------------------------------------------------------------
__device__ __forceinline__ float warpSum(float v) {
    #pragma unroll
    for (int o = 16; o > 0; o >>= 1) v += __shfl_xor_sync(0xffffffffu, v, o);
    return v;
}
__device__ __forceinline__ float warpMax(float v) {
    #pragma unroll
    for (int o = 16; o > 0; o >>= 1) v = fmaxf(v, __shfl_xor_sync(0xffffffffu, v, o));
    return v;
}

// ---------------------------------------------------------------------------
// GroupNorm + transpose to token-major
// ---------------------------------------------------------------------------
__global__ void groupnorm_kernel(const float* __restrict__ qin,
                                 const float* __restrict__ gamma,
                                 const float* __restrict__ beta,
                                 float* __restrict__ out) {
    const int blk = blockIdx.x;
    const int b = blk >> 5;
    const int grp = blk & 31;
    const float* base = qin + ((size_t)b * DIMC + grp * 16) * SPATIAL;

    float s = 0.f, s2 = 0.f;
    for (int i = threadIdx.x; i < 16 * SPATIAL; i += 256) {
        float v = base[i];
        s += v; s2 += v * v;
    }
    __shared__ float red[2][8];
    s = warpSum(s); s2 = warpSum(s2);
    int wid = threadIdx.x >> 5, lid = threadIdx.x & 31;
    if (lid == 0) { red[0][wid] = s; red[1][wid] = s2; }
    __syncthreads();
    if (wid == 0) {
        float a = (lid < 8) ? red[0][lid] : 0.f;
        float c = (lid < 8) ? red[1][lid] : 0.f;
        a = warpSum(a); c = warpSum(c);
        if (lid == 0) { red[0][0] = a; red[1][0] = c; }
    }
    __syncthreads();
    const float mu  = red[0][0] * (1.f / 16384.f);
    const float var = red[1][0] * (1.f / 16384.f) - mu * mu;
    const float inv = rsqrtf(var + 1e-6f);

    for (int i = threadIdx.x; i < 16 * SPATIAL; i += 256) {
        int c = grp * 16 + (i >> 10);
        int sp = i & 1023;
        float v = (base[i] - mu) * inv * gamma[c] + beta[c];
        out[((size_t)(b * SPATIAL + sp)) * DIMC + c] = v;
    }
}

// ---------------------------------------------------------------------------
// LayerNorm over 512-dim rows. One warp per row.
// ---------------------------------------------------------------------------
__global__ void layernorm_kernel(const float* __restrict__ x,
                                 const float* __restrict__ gamma,
                                 const float* __restrict__ beta,
                                 float* __restrict__ out, int rows) {
    int row = blockIdx.x * 8 + (threadIdx.x >> 5);
    if (row >= rows) return;
    int lid = threadIdx.x & 31;
    const float4* xr = (const float4*)(x + (size_t)row * DIMC);

    float4 vals[4];
    float s = 0.f, s2 = 0.f;
    #pragma unroll
    for (int i = 0; i < 4; i++) {
        float4 v = xr[lid + 32 * i];
        vals[i] = v;
        s  += v.x + v.y + v.z + v.w;
        s2 += v.x*v.x + v.y*v.y + v.z*v.z + v.w*v.w;
    }
    s = warpSum(s); s2 = warpSum(s2);
    const float mu  = s * (1.f / 512.f);
    const float inv = rsqrtf(s2 * (1.f / 512.f) - mu * mu + 1e-5f);

    float4* orow = (float4*)(out + (size_t)row * DIMC);
    const float4* g4 = (const float4*)gamma;
    const float4* b4 = (const float4*)beta;
    #pragma unroll
    for (int i = 0; i < 4; i++) {
        int idx = lid + 32 * i;
        float4 v = vals[i], g = g4[idx], b = b4[idx], o;
        o.x = (v.x - mu) * inv * g.x + b.x;
        o.y = (v.y - mu) * inv * g.y + b.y;
        o.z = (v.z - mu) * inv * g.z + b.z;
        o.w = (v.w - mu) * inv * g.w + b.w;
        orow[idx] = o;
    }
}

// ---------------------------------------------------------------------------
// Row softmax (in place). One warp per row.
// ---------------------------------------------------------------------------
__global__ void softmax_kernel(float* __restrict__ S, int rows, int L, int ld) {
    int row = blockIdx.x * 8 + (threadIdx.x >> 5);
    if (row >= rows) return;
    int lid = threadIdx.x & 31;
    float* p = S + (size_t)row * ld;

    float mx = -1e30f;
    for (int i = lid; i < L; i += 32) mx = fmaxf(mx, p[i]);
    mx = warpMax(mx);

    float sum = 0.f;
    for (int i = lid; i < L; i += 32) {
        float e = __expf(p[i] - mx);
        p[i] = e;
        sum += e;
    }
    sum = warpSum(sum);
    const float r = 1.f / sum;
    for (int i = lid; i < L; i += 32) p[i] *= r;
}

// ---------------------------------------------------------------------------
// Weight packing: qkv [512 x 1536] from three [512 x 512] matrices
// ---------------------------------------------------------------------------
__global__ void pack3_kernel(const float* __restrict__ w0,
                             const float* __restrict__ w1,
                             const float* __restrict__ w2,
                             float* __restrict__ out) {
    int i = blockIdx.x * 256 + threadIdx.x;   // over 512*512 float4? do floats4
    // i indexes float4 over 512x1536/4 = 196608
    if (i >= 512 * 1536 / 4) return;
    int row = i / 384;           // 1536/4 = 384 float4 per row
    int c4  = i % 384;
    const float4* src;
    int cc = c4;
    if (c4 < 128)       { src = (const float4*)w0; }
    else if (c4 < 256)  { src = (const float4*)w1; cc = c4 - 128; }
    else                { src = (const float4*)w2; cc = c4 - 256; }
    ((float4*)out)[i] = src[row * 128 + cc];
}

// pack two [1024 x 512] into [1024 x 1024]
__global__ void pack2_kernel(const float* __restrict__ w0,
                             const float* __restrict__ w1,
                             float* __restrict__ out) {
    int i = blockIdx.x * 256 + threadIdx.x;   // float4 over 1024*1024/4
    if (i >= 1024 * 1024 / 4) return;
    int row = i / 256;           // 1024/4 float4 per row
    int c4  = i % 256;
    const float4* src = c4 < 128 ? (const float4*)w0 : (const float4*)w1;
    int cc = c4 < 128 ? c4 : c4 - 128;
    ((float4*)out)[i] = src[row * 128 + cc];
}

// ---------------------------------------------------------------------------
// Final transpose + residual
// ---------------------------------------------------------------------------
__global__ void output_kernel(const float* __restrict__ t,
                              const float* __restrict__ qin,
                              float* __restrict__ out) {
    int i = blockIdx.x * 256 + threadIdx.x;
    if (i >= BATCH * DIMC * SPATIAL) return;
    int sp = i & 1023;
    int bc = i >> 10;
    int c = bc & 511;
    int b = bc >> 9;
    out[i] = t[((size_t)(b * SPATIAL + sp)) * DIMC + c] + qin[i];
}

// ===========================================================================
// TF32 tensor-core GEMM (raw fp32 bits -> tf32 mma, no cvt)
//   emode 0: C = alpha*A@op(B) (+bias) (+Res)
//   emode 1: C = Res * gelu(alpha*A@op(B) + bias)      (GEGLU fusion)
// ===========================================================================
#define BM 128
#define BN 128
#define BK 32
#define STAGE_FLOATS 9216
#define SMEM_BYTES (2 * STAGE_FLOATS * 4)

__device__ __forceinline__ void cp_async16(uint32_t dst, const void* src, int bytes) {
    asm volatile("cp.async.cg.shared.global [%0], [%1], 16, %2;\n"
                 :: "r"(dst), "l"(src), "r"(bytes));
}
__device__ __forceinline__ void cp_commit() {
    asm volatile("cp.async.commit_group;\n");
}
__device__ __forceinline__ void cp_wait_all() {
    asm volatile("cp.async.wait_group 0;\n");
}
__device__ __forceinline__ void mma_tf32(float* d, const uint32_t* a, const uint32_t* b) {
    asm volatile(
        "mma.sync.aligned.m16n8k8.row.col.f32.tf32.tf32.f32 "
        "{%0,%1,%2,%3}, {%4,%5,%6,%7}, {%8,%9}, {%0,%1,%2,%3};"
        : "+f"(d[0]), "+f"(d[1]), "+f"(d[2]), "+f"(d[3])
        : "r"(a[0]), "r"(a[1]), "r"(a[2]), "r"(a[3]), "r"(b[0]), "r"(b[1]));
}

__global__ void __launch_bounds__(256) gemm_tf32_kernel(
    const float* __restrict__ A, int lda, long long sAo, long long sAi,
    const float* __restrict__ B, int ldb, long long sBo, long long sBi,
    float* __restrict__ C, int ldc, long long sCo, long long sCi,
    const float* __restrict__ Res, int ldres,
    const float* __restrict__ bias,
    int M, int N, int K, float alpha, int transB, int zdiv, int emode) {

    extern __shared__ float smem[];

    const int z  = blockIdx.z;
    const int zo = z / zdiv, zi = z % zdiv;
    A += zo * sAo + zi * sAi;
    B += zo * sBo + zi * sBi;
    C += zo * sCo + zi * sCi;

    const int m0 = blockIdx.y * BM;
    const int n0 = blockIdx.x * BN;
    const int tid = threadIdx.x;
    const int warp = tid >> 5;
    const int lane = tid & 31;
    const int g  = lane >> 2;
    const int tg = lane & 3;
    const int wm = (warp >> 2) * 64;
    const int wn = (warp & 3) * 32;

    const uint32_t smem_u32 = (uint32_t)__cvta_generic_to_shared(smem);
    const int nk = (K + BK - 1) / BK;

    float acc[4][4][4];
    #pragma unroll
    for (int i = 0; i < 4; i++)
        #pragma unroll
        for (int j = 0; j < 4; j++)
            #pragma unroll
            for (int r = 0; r < 4; r++) acc[i][j][r] = 0.f;

    auto load_stage = [&](int stage, int k0) {
        const uint32_t abase = smem_u32 + (uint32_t)stage * STAGE_FLOATS * 4;
        #pragma unroll
        for (int i = 0; i < 4; i++) {
            int idx = tid + i * 256;
            int row = idx >> 3;
            int kc  = (idx & 7) * 4;
            int bytes = 0;
            if (m0 + row < M) {
                int rem = K - (k0 + kc);
                bytes = rem >= 4 ? 16 : (rem > 0 ? rem * 4 : 0);
            }
            cp_async16(abase + (uint32_t)(row * 36 + kc) * 4,
                       A + (long long)(m0 + row) * lda + k0 + kc, bytes);
        }
        const uint32_t bbase = abase + 4608u * 4;
        if (!transB) {
            #pragma unroll
            for (int i = 0; i < 4; i++) {
                int idx = tid + i * 256;
                int k  = idx >> 5;
                int nc = (idx & 31) * 4;
                int bytes = 0;
                if (k0 + k < K) {
                    int rem = N - (n0 + nc);
                    bytes = rem >= 4 ? 16 : (rem > 0 ? rem * 4 : 0);
                }
                cp_async16(bbase + (uint32_t)(k * 136 + nc) * 4,
                           B + (long long)(k0 + k) * ldb + n0 + nc, bytes);
            }
        } else {
            #pragma unroll
            for (int i = 0; i < 4; i++) {
                int idx = tid + i * 256;
                int n  = idx >> 3;
                int kc = (idx & 7) * 4;
                int bytes = 0;
                if (n0 + n < N) {
                    int rem = K - (k0 + kc);
                    bytes = rem >= 4 ? 16 : (rem > 0 ? rem * 4 : 0);
                }
                cp_async16(bbase + (uint32_t)(n * 36 + kc) * 4,
                           B + (long long)(n0 + n) * ldb + k0 + kc, bytes);
            }
        }
        cp_commit();
    };

    auto compute_stage = [&](int stage) {
        const uint32_t* As = (const uint32_t*)(smem + stage * STAGE_FLOATS);
        const uint32_t* Bs = As + 4608;
        #pragma unroll
        for (int ks = 0; ks < 4; ks++) {
            const int kk = ks * 8;
            uint32_t afr[4][4];
            #pragma unroll
            for (int mt = 0; mt < 4; mt++) {
                const int mb = wm + mt * 16;
                afr[mt][0] = As[(mb + g)     * 36 + kk + tg];
                afr[mt][1] = As[(mb + g + 8) * 36 + kk + tg];
                afr[mt][2] = As[(mb + g)     * 36 + kk + tg + 4];
                afr[mt][3] = As[(mb + g + 8) * 36 + kk + tg + 4];
            }
            uint32_t bfr[4][2];
            if (!transB) {
                #pragma unroll
                for (int nt = 0; nt < 4; nt++) {
                    const int nb = wn + nt * 8;
                    bfr[nt][0] = Bs[(kk + tg)     * 136 + nb + g];
                    bfr[nt][1] = Bs[(kk + tg + 4) * 136 + nb + g];
                }
            } else {
                #pragma unroll
                for (int nt = 0; nt < 4; nt++) {
                    const int nb = wn + nt * 8;
                    bfr[nt][0] = Bs[(nb + g) * 36 + kk + tg];
                    bfr[nt][1] = Bs[(nb + g) * 36 + kk + tg + 4];
                }
            }
            #pragma unroll
            for (int mt = 0; mt < 4; mt++)
                #pragma unroll
                for (int nt = 0; nt < 4; nt++)
                    mma_tf32(acc[mt][nt], afr[mt], bfr[nt]);
        }
    };

    load_stage(0, 0);
    for (int kt = 0; kt < nk; kt++) {
        cp_wait_all();
        __syncthreads();
        if (kt + 1 < nk) load_stage((kt + 1) & 1, (kt + 1) * BK);
        compute_stage(kt & 1);
        __syncthreads();
    }

    // ---- epilogue ----
    #pragma unroll
    for (int mt = 0; mt < 4; mt++) {
        #pragma unroll
        for (int nt = 0; nt < 4; nt++) {
            const int row0 = m0 + wm + mt * 16 + g;
            const int col0 = n0 + wn + nt * 8 + tg * 2;
            #pragma unroll
            for (int r = 0; r < 4; r++) {
                const int row = row0 + (r >> 1) * 8;
                const int col = col0 + (r & 1);
                if (row < M && col < N) {
                    float v = acc[mt][nt][r] * alpha;
                    if (bias) v += bias[col];
                    if (emode == 1) {
                        float ge = 0.5f * v * (1.f + erff(v * 0.70710678118654752f));
                        v = Res[(long long)row * ldres + col] * ge;
                    } else if (Res) {
                        v += Res[(long long)row * ldres + col];
                    }
                    C[(long long)row * ldc + col] = v;
                }
            }
        }
    }
}

// ---------------------------------------------------------------------------
// Host side
// ---------------------------------------------------------------------------
static void gemm(const float* A, int lda, long long sAo, long long sAi,
                 const float* B, int ldb, long long sBo, long long sBi,
                 float* C, int ldc, long long sCo, long long sCi,
                 const float* Res, int ldres, const float* bias,
                 int M, int N, int K, float alpha, int transB, int zdiv,
                 int batch, int emode = 0) {
    dim3 grid((N + BN - 1) / BN, (M + BM - 1) / BM, batch);
    gemm_tf32_kernel<<<grid, 256, SMEM_BYTES>>>(
        A, lda, sAo, sAi, B, ldb, sBo, sBi,
        C, ldc, sCo, sCi, Res, ldres, bias,
        M, N, K, alpha, transB, zdiv, emode);
}

extern "C" void kernel_launch(void* const* d_in, const int* in_sizes, int n_in,
                              void* d_out, int out_size) {
    const float* in_q     = (const float*)d_in[0];
    const float* in_kv    = (const float*)d_in[1];
    const float* gn_g     = (const float*)d_in[2];
    const float* gn_b     = (const float*)d_in[3];
    const float* ln2_g    = (const float*)d_in[4];
    const float* ln2_b    = (const float*)d_in[5];
    const float* ln3_g    = (const float*)d_in[6];
    const float* ln3_b    = (const float*)d_in[7];
    const float* ln4_g    = (const float*)d_in[8];
    const float* ln4_b    = (const float*)d_in[9];
    const float* fc_in_w  = (const float*)d_in[10];
    const float* fc_in_b  = (const float*)d_in[11];
    const float* fc_out_w = (const float*)d_in[12];
    const float* fc_out_b = (const float*)d_in[13];
    const float* a1_q     = (const float*)d_in[14];
    const float* a1_k     = (const float*)d_in[15];
    const float* a1_v     = (const float*)d_in[16];
    const float* a1_o     = (const float*)d_in[17];
    const float* a1_ob    = (const float*)d_in[18];
    const float* a2_q     = (const float*)d_in[19];
    const float* a2_k     = (const float*)d_in[20];
    const float* a2_v     = (const float*)d_in[21];
    const float* a2_o     = (const float*)d_in[22];
    const float* a2_ob    = (const float*)d_in[23];
    const float* ff_proj_w = (const float*)d_in[24];
    const float* ff_proj_b = (const float*)d_in[25];
    const float* ff_out_w  = (const float*)d_in[26];
    const float* ff_out_b  = (const float*)d_in[27];

    cudaFuncSetAttribute(gemm_tf32_kernel,
                         cudaFuncAttributeMaxDynamicSharedMemorySize, SMEM_BYTES);

    float *x, *t, *q, *qkv, *kv2, *wq, *wk2, *s, *gl;
    cudaGetSymbolAddress((void**)&x,   g_x);
    cudaGetSymbolAddress((void**)&t,   g_t);
    cudaGetSymbolAddress((void**)&q,   g_q);
    cudaGetSymbolAddress((void**)&qkv, g_qkv);
    cudaGetSymbolAddress((void**)&kv2, g_kv2);
    cudaGetSymbolAddress((void**)&wq,  g_wq);
    cudaGetSymbolAddress((void**)&wk2, g_wk2);
    cudaGetSymbolAddress((void**)&s,   g_s);
    cudaGetSymbolAddress((void**)&gl,  g_gl);

    float* out = (float*)d_out;

    // weight packing (cheap, every replay)
    pack3_kernel<<<(512 * 1536 / 4 + 255) / 256, 256>>>(a1_q, a1_k, a1_v, wq);
    pack2_kernel<<<(1024 * 1024 / 4 + 255) / 256, 256>>>(a2_k, a2_v, wk2);

    // 1. GroupNorm + transpose to tokens -> t
    groupnorm_kernel<<<BATCH * 32, 256>>>(in_q, gn_g, gn_b, t);

    // 2. x = t @ fc_in_w + fc_in_b
    gemm(t, 512, 0, 0, fc_in_w, 512, 0, 0, x, 512, 0, 0,
         nullptr, 0, fc_in_b, NTOK, 512, 512, 1.f, 0, 1, 1);

    // ---- self attention ----
    layernorm_kernel<<<NTOK / 8, 256>>>(x, ln2_g, ln2_b, t, NTOK);
    // qkv = t @ wq   [8192 x 1536]
    gemm(t, 512, 0, 0, wq, 1536, 0, 0, qkv, 1536, 0, 0, nullptr, 0, nullptr,
         NTOK, 1536, 512, 1.f, 0, 1, 1);
    // S[b,h] = Qh @ Kh^T * 1/8
    gemm(qkv, 1536, (long long)1024 * 1536, 64,
         qkv + 512, 1536, (long long)1024 * 1536, 64,
         s, 1024, 8388608, 1048576, nullptr, 0, nullptr,
         1024, 1024, 64, 0.125f, 1, 8, 64);
    softmax_kernel<<<(64 * 1024) / 8, 256>>>(s, 64 * 1024, 1024, 1024);
    // O = S @ Vh -> t
    gemm(s, 1024, 8388608, 1048576,
         qkv + 1024, 1536, (long long)1024 * 1536, 64,
         t, 512, 524288, 64, nullptr, 0, nullptr,
         1024, 64, 1024, 1.f, 0, 8, 64);
    gemm(t, 512, 0, 0, a1_o, 512, 0, 0, x, 512, 0, 0,
         x, 512, a1_ob, NTOK, 512, 512, 1.f, 0, 1, 1);

    // ---- cross attention ----
    layernorm_kernel<<<NTOK / 8, 256>>>(x, ln3_g, ln3_b, t, NTOK);
    gemm(t, 512, 0, 0, a2_q, 512, 0, 0, q, 512, 0, 0, nullptr, 0, nullptr,
         NTOK, 512, 512, 1.f, 0, 1, 1);
    // kv2 = in_kv @ wk2   [616 x 1024]
    gemm(in_kv, 1024, 0, 0, wk2, 1024, 0, 0, kv2, 1024, 0, 0,
         nullptr, 0, nullptr, BATCH * KVLEN, 1024, 1024, 1.f, 0, 1, 1);
    // S = Qh @ Kh^T * 1/8, N = 77, ldc = 128 (padded)
    gemm(q, 512, 524288, 64,
         kv2, 1024, (long long)KVLEN * 1024, 64,
         s, 128, 1048576, 131072, nullptr, 0, nullptr,
         1024, KVLEN, 64, 0.125f, 1, 8, 64);
    softmax_kernel<<<(64 * 1024) / 8, 256>>>(s, 64 * 1024, KVLEN, 128);
    gemm(s, 128, 1048576, 131072,
         kv2 + 512, 1024, (long long)KVLEN * 1024, 64,
         t, 512, 524288, 64, nullptr, 0, nullptr,
         1024, 64, KVLEN, 1.f, 0, 8, 64);
    gemm(t, 512, 0, 0, a2_o, 512, 0, 0, x, 512, 0, 0,
         x, 512, a2_ob, NTOK, 512, 512, 1.f, 0, 1, 1);

    // ---- feed-forward (GEGLU, fused into epilogue) ----
    layernorm_kernel<<<NTOK / 8, 256>>>(x, ln4_g, ln4_b, t, NTOK);
    // a-half: gl = t @ Wp[:, 0:2048] + b
    gemm(t, 512, 0, 0, ff_proj_w, 4096, 0, 0, gl, 2048, 0, 0,
         nullptr, 0, ff_proj_b, NTOK, 2048, 512, 1.f, 0, 1, 1);
    // gate-half fused: gl = gl * gelu(t @ Wp[:, 2048:4096] + b)
    gemm(t, 512, 0, 0, ff_proj_w + 2048, 4096, 0, 0, gl, 2048, 0, 0,
         gl, 2048, ff_proj_b + 2048, NTOK, 2048, 512, 1.f, 0, 1, 1, 1);
    // x = gl @ ff_out_w + b + x
    gemm(gl, 2048, 0, 0, ff_out_w, 512, 0, 0, x, 512, 0, 0,
         x, 512, ff_out_b, NTOK, 512, 2048, 1.f, 0, 1, 1);

    // ---- output projection ----
    gemm(x, 512, 0, 0, fc_out_w, 512, 0, 0, t, 512, 0, 0,
         nullptr, 0, fc_out_b, NTOK, 512, 512, 1.f, 0, 1, 1);

    output_kernel<<<(BATCH * DIMC * SPATIAL) / 256, 256>>>(t, in_q, out);
}

// round 4
// speedup vs baseline: 5.1420x; 1.1342x over previous
#include <cuda_runtime.h>
#include <cstdint>
#include <math.h>

// ---------------------------------------------------------------------------
// Problem constants
// ---------------------------------------------------------------------------
#define BATCH   8
#define DIMC    512
#define SPATIAL 1024             // H*W = 32*32
#define NTOK    (BATCH*SPATIAL)  // 8192 tokens
#define HEADS   8
#define HDIM    64
#define KVLEN   77
#define KVDIM   1024

// ---------------------------------------------------------------------------
// Scratch buffers (static device globals: allocation-free)
// ---------------------------------------------------------------------------
__device__ float g_x   [(size_t)NTOK * DIMC];          // running activation
__device__ float g_t   [(size_t)NTOK * DIMC];          // temp / normalized
__device__ float g_q   [(size_t)NTOK * DIMC];          // cross-attn q
__device__ float g_qkv [(size_t)NTOK * 1536];          // packed self-attn q|k|v
__device__ float g_kv2 [(size_t)(BATCH*KVLEN) * 1024]; // packed cross k|v
__device__ float g_wq  [(size_t)512 * 1536];           // packed qkv weights
__device__ float g_wk2 [(size_t)1024 * 1024];          // packed cross kv weights
__device__ float g_gl  [(size_t)NTOK * 2048];          // geglu a-half / output

// ---------------------------------------------------------------------------
// Warp reduction helpers
// ---------------------------------------------------------------------------
__device__ __forceinline__ float warpSum(float v) {
    #pragma unroll
    for (int o = 16; o > 0; o >>= 1) v += __shfl_xor_sync(0xffffffffu, v, o);
    return v;
}

// ---------------------------------------------------------------------------
// GroupNorm + transpose to token-major
// ---------------------------------------------------------------------------
__global__ void groupnorm_kernel(const float* __restrict__ qin,
                                 const float* __restrict__ gamma,
                                 const float* __restrict__ beta,
                                 float* __restrict__ out) {
    const int blk = blockIdx.x;
    const int b = blk >> 5;
    const int grp = blk & 31;
    const float* base = qin + ((size_t)b * DIMC + grp * 16) * SPATIAL;

    float s = 0.f, s2 = 0.f;
    for (int i = threadIdx.x; i < 16 * SPATIAL; i += 256) {
        float v = base[i];
        s += v; s2 += v * v;
    }
    __shared__ float red[2][8];
    s = warpSum(s); s2 = warpSum(s2);
    int wid = threadIdx.x >> 5, lid = threadIdx.x & 31;
    if (lid == 0) { red[0][wid] = s; red[1][wid] = s2; }
    __syncthreads();
    if (wid == 0) {
        float a = (lid < 8) ? red[0][lid] : 0.f;
        float c = (lid < 8) ? red[1][lid] : 0.f;
        a = warpSum(a); c = warpSum(c);
        if (lid == 0) { red[0][0] = a; red[1][0] = c; }
    }
    __syncthreads();
    const float mu  = red[0][0] * (1.f / 16384.f);
    const float var = red[1][0] * (1.f / 16384.f) - mu * mu;
    const float inv = rsqrtf(var + 1e-6f);

    for (int i = threadIdx.x; i < 16 * SPATIAL; i += 256) {
        int c = grp * 16 + (i >> 10);
        int sp = i & 1023;
        float v = (base[i] - mu) * inv * gamma[c] + beta[c];
        out[((size_t)(b * SPATIAL + sp)) * DIMC + c] = v;
    }
}

// ---------------------------------------------------------------------------
// LayerNorm over 512-dim rows. One warp per row.
// ---------------------------------------------------------------------------
__global__ void layernorm_kernel(const float* __restrict__ x,
                                 const float* __restrict__ gamma,
                                 const float* __restrict__ beta,
                                 float* __restrict__ out, int rows) {
    int row = blockIdx.x * 8 + (threadIdx.x >> 5);
    if (row >= rows) return;
    int lid = threadIdx.x & 31;
    const float4* xr = (const float4*)(x + (size_t)row * DIMC);

    float4 vals[4];
    float s = 0.f, s2 = 0.f;
    #pragma unroll
    for (int i = 0; i < 4; i++) {
        float4 v = xr[lid + 32 * i];
        vals[i] = v;
        s  += v.x + v.y + v.z + v.w;
        s2 += v.x*v.x + v.y*v.y + v.z*v.z + v.w*v.w;
    }
    s = warpSum(s); s2 = warpSum(s2);
    const float mu  = s * (1.f / 512.f);
    const float inv = rsqrtf(s2 * (1.f / 512.f) - mu * mu + 1e-5f);

    float4* orow = (float4*)(out + (size_t)row * DIMC);
    const float4* g4 = (const float4*)gamma;
    const float4* b4 = (const float4*)beta;
    #pragma unroll
    for (int i = 0; i < 4; i++) {
        int idx = lid + 32 * i;
        float4 v = vals[i], g = g4[idx], b = b4[idx], o;
        o.x = (v.x - mu) * inv * g.x + b.x;
        o.y = (v.y - mu) * inv * g.y + b.y;
        o.z = (v.z - mu) * inv * g.z + b.z;
        o.w = (v.w - mu) * inv * g.w + b.w;
        orow[idx] = o;
    }
}

// ---------------------------------------------------------------------------
// Weight packing
// ---------------------------------------------------------------------------
__global__ void pack3_kernel(const float* __restrict__ w0,
                             const float* __restrict__ w1,
                             const float* __restrict__ w2,
                             float* __restrict__ out) {
    int i = blockIdx.x * 256 + threadIdx.x;
    if (i >= 512 * 1536 / 4) return;
    int row = i / 384;
    int c4  = i % 384;
    const float4* src;
    int cc = c4;
    if (c4 < 128)       { src = (const float4*)w0; }
    else if (c4 < 256)  { src = (const float4*)w1; cc = c4 - 128; }
    else                { src = (const float4*)w2; cc = c4 - 256; }
    ((float4*)out)[i] = src[row * 128 + cc];
}

__global__ void pack2_kernel(const float* __restrict__ w0,
                             const float* __restrict__ w1,
                             float* __restrict__ out) {
    int i = blockIdx.x * 256 + threadIdx.x;
    if (i >= 1024 * 1024 / 4) return;
    int row = i / 256;
    int c4  = i % 256;
    const float4* src = c4 < 128 ? (const float4*)w0 : (const float4*)w1;
    int cc = c4 < 128 ? c4 : c4 - 128;
    ((float4*)out)[i] = src[row * 128 + cc];
}

// ---------------------------------------------------------------------------
// Final transpose + residual
// ---------------------------------------------------------------------------
__global__ void output_kernel(const float* __restrict__ t,
                              const float* __restrict__ qin,
                              float* __restrict__ out) {
    int i = blockIdx.x * 256 + threadIdx.x;
    if (i >= BATCH * DIMC * SPATIAL) return;
    int sp = i & 1023;
    int bc = i >> 10;
    int c = bc & 511;
    int b = bc >> 9;
    out[i] = t[((size_t)(b * SPATIAL + sp)) * DIMC + c] + qin[i];
}

// ---------------------------------------------------------------------------
// mma helper (tf32, raw fp32 bits, truncation)
// ---------------------------------------------------------------------------
__device__ __forceinline__ void mma_tf32(float* d, const uint32_t* a, const uint32_t* b) {
    asm volatile(
        "mma.sync.aligned.m16n8k8.row.col.f32.tf32.tf32.f32 "
        "{%0,%1,%2,%3}, {%4,%5,%6,%7}, {%8,%9}, {%0,%1,%2,%3};"
        : "+f"(d[0]), "+f"(d[1]), "+f"(d[2]), "+f"(d[3])
        : "r"(a[0]), "r"(a[1]), "r"(a[2]), "r"(a[3]), "r"(b[0]), "r"(b[1]));
}

// ===========================================================================
// Fused flash self-attention.
//   qkv packed [8192 x 1536] (q|k|v), heads of 64. Out -> t [8192 x 512].
//   Grid: (8 q-tiles, 64 b*h). 256 threads = 8 warps x 16 rows.
//   Per warp: S tile 16x128 (full kv chunk), online softmax, P via smem,
//   O accum 16x64 in registers.
// ===========================================================================
#define FSTR 68     // Q/K smem row stride
#define PSTR 132    // P / Vt smem row stride
// smem floats: sQ 128*68, sK 128*68, sVt 64*132, sP 128*132
#define FS_SQ   0
#define FS_SK   (128*FSTR)
#define FS_SVT  (FS_SK + 128*FSTR)
#define FS_SP   (FS_SVT + 64*PSTR)
#define FS_TOTAL (FS_SP + 128*PSTR)

__global__ void __launch_bounds__(256) flash_self_kernel(
    const float* __restrict__ qkv, float* __restrict__ outp) {
    extern __shared__ float sm[];
    float* sQ  = sm + FS_SQ;
    float* sK  = sm + FS_SK;
    float* sVt = sm + FS_SVT;
    float* sP  = sm + FS_SP;

    const int b  = blockIdx.y >> 3;
    const int h  = blockIdx.y & 7;
    const int q0 = blockIdx.x * 128;
    const int tid = threadIdx.x;
    const int warp = tid >> 5;
    const int lane = tid & 31;
    const int g  = lane >> 2;
    const int tg = lane & 3;
    const int wm = warp * 16;

    // ---- load Q tile, scaled by 1/8 ----
    for (int i = tid; i < 2048; i += 256) {
        int row = i >> 4;
        int c4  = (i & 15) * 4;
        const float4 v = *(const float4*)(qkv +
            (size_t)(b * 1024 + q0 + row) * 1536 + h * 64 + c4);
        float* d = sQ + row * FSTR + c4;
        d[0] = v.x * 0.125f; d[1] = v.y * 0.125f;
        d[2] = v.z * 0.125f; d[3] = v.w * 0.125f;
    }
    __syncthreads();

    // ---- cache Q fragments (warp rows wm..wm+15, all 64 k) ----
    uint32_t qf[8][4];
    {
        const uint32_t* Qs = (const uint32_t*)sQ;
        #pragma unroll
        for (int kc = 0; kc < 8; kc++) {
            const int kk = kc * 8;
            qf[kc][0] = Qs[(wm + g)     * FSTR + kk + tg];
            qf[kc][1] = Qs[(wm + g + 8) * FSTR + kk + tg];
            qf[kc][2] = Qs[(wm + g)     * FSTR + kk + tg + 4];
            qf[kc][3] = Qs[(wm + g + 8) * FSTR + kk + tg + 4];
        }
    }

    float m_[2] = {-1e30f, -1e30f};
    float l_[2] = {0.f, 0.f};
    float acco[8][4];
    #pragma unroll
    for (int i = 0; i < 8; i++)
        #pragma unroll
        for (int r = 0; r < 4; r++) acco[i][r] = 0.f;

    for (int j = 0; j < 8; j++) {
        // ---- load K tile + V tile (transposed) ----
        for (int i = tid; i < 2048; i += 256) {
            int row = i >> 4;
            int c4  = (i & 15) * 4;
            const float* base = qkv + (size_t)(b * 1024 + j * 128 + row) * 1536 + h * 64;
            const float4 kv4 = *(const float4*)(base + 512 + c4);
            float* dk = sK + row * FSTR + c4;
            dk[0] = kv4.x; dk[1] = kv4.y; dk[2] = kv4.z; dk[3] = kv4.w;
            const float4 vv = *(const float4*)(base + 1024 + c4);
            sVt[(c4 + 0) * PSTR + row] = vv.x;
            sVt[(c4 + 1) * PSTR + row] = vv.y;
            sVt[(c4 + 2) * PSTR + row] = vv.z;
            sVt[(c4 + 3) * PSTR + row] = vv.w;
        }
        __syncthreads();

        // ---- S = Q @ K^T (16 x 128 per warp) ----
        float accs[16][4];
        #pragma unroll
        for (int nt = 0; nt < 16; nt++)
            #pragma unroll
            for (int r = 0; r < 4; r++) accs[nt][r] = 0.f;

        const uint32_t* Ks = (const uint32_t*)sK;
        #pragma unroll
        for (int kc = 0; kc < 8; kc++) {
            const int kk = kc * 8;
            #pragma unroll
            for (int nt = 0; nt < 16; nt++) {
                const int nb = nt * 8;
                uint32_t bf[2];
                bf[0] = Ks[(nb + g) * FSTR + kk + tg];
                bf[1] = Ks[(nb + g) * FSTR + kk + tg + 4];
                mma_tf32(accs[nt], qf[kc], bf);
            }
        }

        // ---- online softmax update ----
        float mx0 = -1e30f, mx1 = -1e30f;
        #pragma unroll
        for (int nt = 0; nt < 16; nt++) {
            mx0 = fmaxf(mx0, fmaxf(accs[nt][0], accs[nt][1]));
            mx1 = fmaxf(mx1, fmaxf(accs[nt][2], accs[nt][3]));
        }
        mx0 = fmaxf(mx0, __shfl_xor_sync(0xffffffffu, mx0, 1));
        mx0 = fmaxf(mx0, __shfl_xor_sync(0xffffffffu, mx0, 2));
        mx1 = fmaxf(mx1, __shfl_xor_sync(0xffffffffu, mx1, 1));
        mx1 = fmaxf(mx1, __shfl_xor_sync(0xffffffffu, mx1, 2));
        const float mn0 = fmaxf(m_[0], mx0);
        const float mn1 = fmaxf(m_[1], mx1);
        const float c0 = __expf(m_[0] - mn0);
        const float c1 = __expf(m_[1] - mn1);
        l_[0] *= c0; l_[1] *= c1;
        #pragma unroll
        for (int nt = 0; nt < 8; nt++) {
            acco[nt][0] *= c0; acco[nt][1] *= c0;
            acco[nt][2] *= c1; acco[nt][3] *= c1;
        }
        float rs0 = 0.f, rs1 = 0.f;
        float* p0 = sP + (wm + g) * PSTR + 2 * tg;
        float* p1 = sP + (wm + g + 8) * PSTR + 2 * tg;
        #pragma unroll
        for (int nt = 0; nt < 16; nt++) {
            const float e0 = __expf(accs[nt][0] - mn0);
            const float e1 = __expf(accs[nt][1] - mn0);
            const float e2 = __expf(accs[nt][2] - mn1);
            const float e3 = __expf(accs[nt][3] - mn1);
            rs0 += e0 + e1; rs1 += e2 + e3;
            p0[nt * 8 + 0] = e0; p0[nt * 8 + 1] = e1;
            p1[nt * 8 + 0] = e2; p1[nt * 8 + 1] = e3;
        }
        rs0 += __shfl_xor_sync(0xffffffffu, rs0, 1);
        rs0 += __shfl_xor_sync(0xffffffffu, rs0, 2);
        rs1 += __shfl_xor_sync(0xffffffffu, rs1, 1);
        rs1 += __shfl_xor_sync(0xffffffffu, rs1, 2);
        l_[0] += rs0; l_[1] += rs1;
        m_[0] = mn0; m_[1] = mn1;
        __syncwarp();

        // ---- O += P @ V  (K dim = 128) ----
        const uint32_t* Ps = (const uint32_t*)sP;
        const uint32_t* Vs = (const uint32_t*)sVt;
        #pragma unroll
        for (int kc = 0; kc < 16; kc++) {
            const int kk = kc * 8;
            uint32_t af[4];
            af[0] = Ps[(wm + g)     * PSTR + kk + tg];
            af[1] = Ps[(wm + g + 8) * PSTR + kk + tg];
            af[2] = Ps[(wm + g)     * PSTR + kk + tg + 4];
            af[3] = Ps[(wm + g + 8) * PSTR + kk + tg + 4];
            #pragma unroll
            for (int nt = 0; nt < 8; nt++) {
                const int nb = nt * 8;
                uint32_t bf[2];
                bf[0] = Vs[(nb + g) * PSTR + kk + tg];
                bf[1] = Vs[(nb + g) * PSTR + kk + tg + 4];
                mma_tf32(acco[nt], af, bf);
            }
        }
        __syncthreads();   // before overwriting sK/sVt next iter
    }

    // ---- epilogue: O /= l, write to outp (head-packed 512) ----
    const float i0 = 1.f / l_[0];
    const float i1 = 1.f / l_[1];
    const int row0 = b * 1024 + q0 + wm + g;
    #pragma unroll
    for (int nt = 0; nt < 8; nt++) {
        const int col = h * 64 + nt * 8 + 2 * tg;
        outp[(size_t)row0 * 512 + col]           = acco[nt][0] * i0;
        outp[(size_t)row0 * 512 + col + 1]       = acco[nt][1] * i0;
        outp[(size_t)(row0 + 8) * 512 + col]     = acco[nt][2] * i1;
        outp[(size_t)(row0 + 8) * 512 + col + 1] = acco[nt][3] * i1;
    }
}

// ===========================================================================
// Fused flash cross-attention. kv len 77 (padded to 80), single tile.
//   q: [8192 x 512] (head-packed). kv2: [616 x 1024] = k|v.  Out -> t.
// ===========================================================================
#define CSTR 84
#define CF_SQ   0
#define CF_SK   (128*FSTR)
#define CF_SVT  (CF_SK + 80*FSTR)
#define CF_SP   (CF_SVT + 64*CSTR)
#define CF_TOTAL (CF_SP + 128*CSTR)

__global__ void __launch_bounds__(256) flash_cross_kernel(
    const float* __restrict__ qsrc, const float* __restrict__ kv2,
    float* __restrict__ outp) {
    extern __shared__ float sm[];
    float* sQ  = sm + CF_SQ;
    float* sK  = sm + CF_SK;
    float* sVt = sm + CF_SVT;
    float* sP  = sm + CF_SP;

    const int b  = blockIdx.y >> 3;
    const int h  = blockIdx.y & 7;
    const int q0 = blockIdx.x * 128;
    const int tid = threadIdx.x;
    const int warp = tid >> 5;
    const int lane = tid & 31;
    const int g  = lane >> 2;
    const int tg = lane & 3;
    const int wm = warp * 16;

    // ---- load Q (scaled) ----
    for (int i = tid; i < 2048; i += 256) {
        int row = i >> 4;
        int c4  = (i & 15) * 4;
        const float4 v = *(const float4*)(qsrc +
            (size_t)(b * 1024 + q0 + row) * 512 + h * 64 + c4);
        float* d = sQ + row * FSTR + c4;
        d[0] = v.x * 0.125f; d[1] = v.y * 0.125f;
        d[2] = v.z * 0.125f; d[3] = v.w * 0.125f;
    }
    // ---- load K (80 rows, pad zero) + V transposed ----
    for (int i = tid; i < 1280; i += 256) {
        int row = i >> 4;
        int c4  = (i & 15) * 4;
        float4 kk = make_float4(0.f, 0.f, 0.f, 0.f);
        float4 vv = make_float4(0.f, 0.f, 0.f, 0.f);
        if (row < KVLEN) {
            const float* base = kv2 + (size_t)(b * KVLEN + row) * 1024 + h * 64;
            kk = *(const float4*)(base + c4);
            vv = *(const float4*)(base + 512 + c4);
        }
        float* dk = sK + row * FSTR + c4;
        dk[0] = kk.x; dk[1] = kk.y; dk[2] = kk.z; dk[3] = kk.w;
        sVt[(c4 + 0) * CSTR + row] = vv.x;
        sVt[(c4 + 1) * CSTR + row] = vv.y;
        sVt[(c4 + 2) * CSTR + row] = vv.z;
        sVt[(c4 + 3) * CSTR + row] = vv.w;
    }
    __syncthreads();

    // ---- S = Q @ K^T  (16 x 80 per warp) ----
    uint32_t qf[8][4];
    const uint32_t* Qs = (const uint32_t*)sQ;
    #pragma unroll
    for (int kc = 0; kc < 8; kc++) {
        const int kk = kc * 8;
        qf[kc][0] = Qs[(wm + g)     * FSTR + kk + tg];
        qf[kc][1] = Qs[(wm + g + 8) * FSTR + kk + tg];
        qf[kc][2] = Qs[(wm + g)     * FSTR + kk + tg + 4];
        qf[kc][3] = Qs[(wm + g + 8) * FSTR + kk + tg + 4];
    }
    float accs[10][4];
    #pragma unroll
    for (int nt = 0; nt < 10; nt++)
        #pragma unroll
        for (int r = 0; r < 4; r++) accs[nt][r] = 0.f;
    const uint32_t* Ks = (const uint32_t*)sK;
    #pragma unroll
    for (int kc = 0; kc < 8; kc++) {
        const int kk = kc * 8;
        #pragma unroll
        for (int nt = 0; nt < 10; nt++) {
            const int nb = nt * 8;
            uint32_t bf[2];
            bf[0] = Ks[(nb + g) * FSTR + kk + tg];
            bf[1] = Ks[(nb + g) * FSTR + kk + tg + 4];
            mma_tf32(accs[nt], qf[kc], bf);
        }
    }

    // ---- mask cols >= 77, softmax ----
    #pragma unroll
    for (int nt = 0; nt < 10; nt++) {
        const int col0 = nt * 8 + 2 * tg;
        if (col0 >= KVLEN)     { accs[nt][0] = -1e30f; accs[nt][2] = -1e30f; }
        if (col0 + 1 >= KVLEN) { accs[nt][1] = -1e30f; accs[nt][3] = -1e30f; }
    }
    float mx0 = -1e30f, mx1 = -1e30f;
    #pragma unroll
    for (int nt = 0; nt < 10; nt++) {
        mx0 = fmaxf(mx0, fmaxf(accs[nt][0], accs[nt][1]));
        mx1 = fmaxf(mx1, fmaxf(accs[nt][2], accs[nt][3]));
    }
    mx0 = fmaxf(mx0, __shfl_xor_sync(0xffffffffu, mx0, 1));
    mx0 = fmaxf(mx0, __shfl_xor_sync(0xffffffffu, mx0, 2));
    mx1 = fmaxf(mx1, __shfl_xor_sync(0xffffffffu, mx1, 1));
    mx1 = fmaxf(mx1, __shfl_xor_sync(0xffffffffu, mx1, 2));

    float rs0 = 0.f, rs1 = 0.f;
    float* p0 = sP + (wm + g) * CSTR + 2 * tg;
    float* p1 = sP + (wm + g + 8) * CSTR + 2 * tg;
    #pragma unroll
    for (int nt = 0; nt < 10; nt++) {
        const float e0 = __expf(accs[nt][0] - mx0);
        const float e1 = __expf(accs[nt][1] - mx0);
        const float e2 = __expf(accs[nt][2] - mx1);
        const float e3 = __expf(accs[nt][3] - mx1);
        rs0 += e0 + e1; rs1 += e2 + e3;
        p0[nt * 8 + 0] = e0; p0[nt * 8 + 1] = e1;
        p1[nt * 8 + 0] = e2; p1[nt * 8 + 1] = e3;
    }
    rs0 += __shfl_xor_sync(0xffffffffu, rs0, 1);
    rs0 += __shfl_xor_sync(0xffffffffu, rs0, 2);
    rs1 += __shfl_xor_sync(0xffffffffu, rs1, 1);
    rs1 += __shfl_xor_sync(0xffffffffu, rs1, 2);
    __syncwarp();

    // ---- O = P @ V  (K dim = 80) ----
    float acco[8][4];
    #pragma unroll
    for (int nt = 0; nt < 8; nt++)
        #pragma unroll
        for (int r = 0; r < 4; r++) acco[nt][r] = 0.f;
    const uint32_t* Ps = (const uint32_t*)sP;
    const uint32_t* Vs = (const uint32_t*)sVt;
    #pragma unroll
    for (int kc = 0; kc < 10; kc++) {
        const int kk = kc * 8;
        uint32_t af[4];
        af[0] = Ps[(wm + g)     * CSTR + kk + tg];
        af[1] = Ps[(wm + g + 8) * CSTR + kk + tg];
        af[2] = Ps[(wm + g)     * CSTR + kk + tg + 4];
        af[3] = Ps[(wm + g + 8) * CSTR + kk + tg + 4];
        #pragma unroll
        for (int nt = 0; nt < 8; nt++) {
            const int nb = nt * 8;
            uint32_t bf[2];
            bf[0] = Vs[(nb + g) * CSTR + kk + tg];
            bf[1] = Vs[(nb + g) * CSTR + kk + tg + 4];
            mma_tf32(acco[nt], af, bf);
        }
    }

    const float i0 = 1.f / rs0;
    const float i1 = 1.f / rs1;
    const int row0 = b * 1024 + q0 + wm + g;
    #pragma unroll
    for (int nt = 0; nt < 8; nt++) {
        const int col = h * 64 + nt * 8 + 2 * tg;
        outp[(size_t)row0 * 512 + col]           = acco[nt][0] * i0;
        outp[(size_t)row0 * 512 + col + 1]       = acco[nt][1] * i0;
        outp[(size_t)(row0 + 8) * 512 + col]     = acco[nt][2] * i1;
        outp[(size_t)(row0 + 8) * 512 + col + 1] = acco[nt][3] * i1;
    }
}

// ===========================================================================
// TF32 tensor-core GEMM (raw fp32 bits -> tf32 mma)
//   emode 0: C = alpha*A@op(B) (+bias) (+Res)
//   emode 1: C = Res * gelu(alpha*A@op(B) + bias)      (GEGLU fusion)
// ===========================================================================
#define BM 128
#define BN 128
#define BK 32
#define STAGE_FLOATS 9216
#define SMEM_BYTES (2 * STAGE_FLOATS * 4)

__device__ __forceinline__ void cp_async16(uint32_t dst, const void* src, int bytes) {
    asm volatile("cp.async.cg.shared.global [%0], [%1], 16, %2;\n"
                 :: "r"(dst), "l"(src), "r"(bytes));
}
__device__ __forceinline__ void cp_commit() {
    asm volatile("cp.async.commit_group;\n");
}
__device__ __forceinline__ void cp_wait_all() {
    asm volatile("cp.async.wait_group 0;\n");
}

__global__ void __launch_bounds__(256) gemm_tf32_kernel(
    const float* __restrict__ A, int lda, long long sAo, long long sAi,
    const float* __restrict__ B, int ldb, long long sBo, long long sBi,
    float* __restrict__ C, int ldc, long long sCo, long long sCi,
    const float* __restrict__ Res, int ldres,
    const float* __restrict__ bias,
    int M, int N, int K, float alpha, int transB, int zdiv, int emode) {

    extern __shared__ float smem[];

    const int z  = blockIdx.z;
    const int zo = z / zdiv, zi = z % zdiv;
    A += zo * sAo + zi * sAi;
    B += zo * sBo + zi * sBi;
    C += zo * sCo + zi * sCi;

    const int m0 = blockIdx.y * BM;
    const int n0 = blockIdx.x * BN;
    const int tid = threadIdx.x;
    const int warp = tid >> 5;
    const int lane = tid & 31;
    const int g  = lane >> 2;
    const int tg = lane & 3;
    const int wm = (warp >> 2) * 64;
    const int wn = (warp & 3) * 32;

    const uint32_t smem_u32 = (uint32_t)__cvta_generic_to_shared(smem);
    const int nk = (K + BK - 1) / BK;

    float acc[4][4][4];
    #pragma unroll
    for (int i = 0; i < 4; i++)
        #pragma unroll
        for (int j = 0; j < 4; j++)
            #pragma unroll
            for (int r = 0; r < 4; r++) acc[i][j][r] = 0.f;

    auto load_stage = [&](int stage, int k0) {
        const uint32_t abase = smem_u32 + (uint32_t)stage * STAGE_FLOATS * 4;
        #pragma unroll
        for (int i = 0; i < 4; i++) {
            int idx = tid + i * 256;
            int row = idx >> 3;
            int kc  = (idx & 7) * 4;
            int bytes = 0;
            if (m0 + row < M) {
                int rem = K - (k0 + kc);
                bytes = rem >= 4 ? 16 : (rem > 0 ? rem * 4 : 0);
            }
            cp_async16(abase + (uint32_t)(row * 36 + kc) * 4,
                       A + (long long)(m0 + row) * lda + k0 + kc, bytes);
        }
        const uint32_t bbase = abase + 4608u * 4;
        if (!transB) {
            #pragma unroll
            for (int i = 0; i < 4; i++) {
                int idx = tid + i * 256;
                int k  = idx >> 5;
                int nc = (idx & 31) * 4;
                int bytes = 0;
                if (k0 + k < K) {
                    int rem = N - (n0 + nc);
                    bytes = rem >= 4 ? 16 : (rem > 0 ? rem * 4 : 0);
                }
                cp_async16(bbase + (uint32_t)(k * 136 + nc) * 4,
                           B + (long long)(k0 + k) * ldb + n0 + nc, bytes);
            }
        } else {
            #pragma unroll
            for (int i = 0; i < 4; i++) {
                int idx = tid + i * 256;
                int n  = idx >> 3;
                int kc = (idx & 7) * 4;
                int bytes = 0;
                if (n0 + n < N) {
                    int rem = K - (k0 + kc);
                    bytes = rem >= 4 ? 16 : (rem > 0 ? rem * 4 : 0);
                }
                cp_async16(bbase + (uint32_t)(n * 36 + kc) * 4,
                           B + (long long)(n0 + n) * ldb + k0 + kc, bytes);
            }
        }
        cp_commit();
    };

    auto compute_stage = [&](int stage) {
        const uint32_t* As = (const uint32_t*)(smem + stage * STAGE_FLOATS);
        const uint32_t* Bs = As + 4608;
        #pragma unroll
        for (int ks = 0; ks < 4; ks++) {
            const int kk = ks * 8;
            uint32_t afr[4][4];
            #pragma unroll
            for (int mt = 0; mt < 4; mt++) {
                const int mb = wm + mt * 16;
                afr[mt][0] = As[(mb + g)     * 36 + kk + tg];
                afr[mt][1] = As[(mb + g + 8) * 36 + kk + tg];
                afr[mt][2] = As[(mb + g)     * 36 + kk + tg + 4];
                afr[mt][3] = As[(mb + g + 8) * 36 + kk + tg + 4];
            }
            uint32_t bfr[4][2];
            if (!transB) {
                #pragma unroll
                for (int nt = 0; nt < 4; nt++) {
                    const int nb = wn + nt * 8;
                    bfr[nt][0] = Bs[(kk + tg)     * 136 + nb + g];
                    bfr[nt][1] = Bs[(kk + tg + 4) * 136 + nb + g];
                }
            } else {
                #pragma unroll
                for (int nt = 0; nt < 4; nt++) {
                    const int nb = wn + nt * 8;
                    bfr[nt][0] = Bs[(nb + g) * 36 + kk + tg];
                    bfr[nt][1] = Bs[(nb + g) * 36 + kk + tg + 4];
                }
            }
            #pragma unroll
            for (int mt = 0; mt < 4; mt++)
                #pragma unroll
                for (int nt = 0; nt < 4; nt++)
                    mma_tf32(acc[mt][nt], afr[mt], bfr[nt]);
        }
    };

    load_stage(0, 0);
    for (int kt = 0; kt < nk; kt++) {
        cp_wait_all();
        __syncthreads();
        if (kt + 1 < nk) load_stage((kt + 1) & 1, (kt + 1) * BK);
        compute_stage(kt & 1);
        __syncthreads();
    }

    #pragma unroll
    for (int mt = 0; mt < 4; mt++) {
        #pragma unroll
        for (int nt = 0; nt < 4; nt++) {
            const int row0 = m0 + wm + mt * 16 + g;
            const int col0 = n0 + wn + nt * 8 + tg * 2;
            #pragma unroll
            for (int r = 0; r < 4; r++) {
                const int row = row0 + (r >> 1) * 8;
                const int col = col0 + (r & 1);
                if (row < M && col < N) {
                    float v = acc[mt][nt][r] * alpha;
                    if (bias) v += bias[col];
                    if (emode == 1) {
                        float ge = 0.5f * v * (1.f + erff(v * 0.70710678118654752f));
                        v = Res[(long long)row * ldres + col] * ge;
                    } else if (Res) {
                        v += Res[(long long)row * ldres + col];
                    }
                    C[(long long)row * ldc + col] = v;
                }
            }
        }
    }
}

// ---------------------------------------------------------------------------
// Host side
// ---------------------------------------------------------------------------
static void gemm(const float* A, int lda, long long sAo, long long sAi,
                 const float* B, int ldb, long long sBo, long long sBi,
                 float* C, int ldc, long long sCo, long long sCi,
                 const float* Res, int ldres, const float* bias,
                 int M, int N, int K, float alpha, int transB, int zdiv,
                 int batch, int emode = 0) {
    dim3 grid((N + BN - 1) / BN, (M + BM - 1) / BM, batch);
    gemm_tf32_kernel<<<grid, 256, SMEM_BYTES>>>(
        A, lda, sAo, sAi, B, ldb, sBo, sBi,
        C, ldc, sCo, sCi, Res, ldres, bias,
        M, N, K, alpha, transB, zdiv, emode);
}

extern "C" void kernel_launch(void* const* d_in, const int* in_sizes, int n_in,
                              void* d_out, int out_size) {
    const float* in_q     = (const float*)d_in[0];
    const float* in_kv    = (const float*)d_in[1];
    const float* gn_g     = (const float*)d_in[2];
    const float* gn_b     = (const float*)d_in[3];
    const float* ln2_g    = (const float*)d_in[4];
    const float* ln2_b    = (const float*)d_in[5];
    const float* ln3_g    = (const float*)d_in[6];
    const float* ln3_b    = (const float*)d_in[7];
    const float* ln4_g    = (const float*)d_in[8];
    const float* ln4_b    = (const float*)d_in[9];
    const float* fc_in_w  = (const float*)d_in[10];
    const float* fc_in_b  = (const float*)d_in[11];
    const float* fc_out_w = (const float*)d_in[12];
    const float* fc_out_b = (const float*)d_in[13];
    const float* a1_q     = (const float*)d_in[14];
    const float* a1_k     = (const float*)d_in[15];
    const float* a1_v     = (const float*)d_in[16];
    const float* a1_o     = (const float*)d_in[17];
    const float* a1_ob    = (const float*)d_in[18];
    const float* a2_q     = (const float*)d_in[19];
    const float* a2_k     = (const float*)d_in[20];
    const float* a2_v     = (const float*)d_in[21];
    const float* a2_o     = (const float*)d_in[22];
    const float* a2_ob    = (const float*)d_in[23];
    const float* ff_proj_w = (const float*)d_in[24];
    const float* ff_proj_b = (const float*)d_in[25];
    const float* ff_out_w  = (const float*)d_in[26];
    const float* ff_out_b  = (const float*)d_in[27];

    cudaFuncSetAttribute(gemm_tf32_kernel,
                         cudaFuncAttributeMaxDynamicSharedMemorySize, SMEM_BYTES);
    cudaFuncSetAttribute(flash_self_kernel,
                         cudaFuncAttributeMaxDynamicSharedMemorySize, FS_TOTAL * 4);
    cudaFuncSetAttribute(flash_cross_kernel,
                         cudaFuncAttributeMaxDynamicSharedMemorySize, CF_TOTAL * 4);

    float *x, *t, *q, *qkv, *kv2, *wq, *wk2, *gl;
    cudaGetSymbolAddress((void**)&x,   g_x);
    cudaGetSymbolAddress((void**)&t,   g_t);
    cudaGetSymbolAddress((void**)&q,   g_q);
    cudaGetSymbolAddress((void**)&qkv, g_qkv);
    cudaGetSymbolAddress((void**)&kv2, g_kv2);
    cudaGetSymbolAddress((void**)&wq,  g_wq);
    cudaGetSymbolAddress((void**)&wk2, g_wk2);
    cudaGetSymbolAddress((void**)&gl,  g_gl);

    float* out = (float*)d_out;

    // weight packing
    pack3_kernel<<<(512 * 1536 / 4 + 255) / 256, 256>>>(a1_q, a1_k, a1_v, wq);
    pack2_kernel<<<(1024 * 1024 / 4 + 255) / 256, 256>>>(a2_k, a2_v, wk2);

    // 1. GroupNorm + transpose to tokens -> t
    groupnorm_kernel<<<BATCH * 32, 256>>>(in_q, gn_g, gn_b, t);

    // 2. x = t @ fc_in_w + fc_in_b
    gemm(t, 512, 0, 0, fc_in_w, 512, 0, 0, x, 512, 0, 0,
         nullptr, 0, fc_in_b, NTOK, 512, 512, 1.f, 0, 1, 1);

    // ---- self attention ----
    layernorm_kernel<<<NTOK / 8, 256>>>(x, ln2_g, ln2_b, t, NTOK);
    gemm(t, 512, 0, 0, wq, 1536, 0, 0, qkv, 1536, 0, 0, nullptr, 0, nullptr,
         NTOK, 1536, 512, 1.f, 0, 1, 1);
    {
        dim3 grid(8, 64);
        flash_self_kernel<<<grid, 256, FS_TOTAL * 4>>>(qkv, t);
    }
    gemm(t, 512, 0, 0, a1_o, 512, 0, 0, x, 512, 0, 0,
         x, 512, a1_ob, NTOK, 512, 512, 1.f, 0, 1, 1);

    // ---- cross attention ----
    layernorm_kernel<<<NTOK / 8, 256>>>(x, ln3_g, ln3_b, t, NTOK);
    gemm(t, 512, 0, 0, a2_q, 512, 0, 0, q, 512, 0, 0, nullptr, 0, nullptr,
         NTOK, 512, 512, 1.f, 0, 1, 1);
    gemm(in_kv, 1024, 0, 0, wk2, 1024, 0, 0, kv2, 1024, 0, 0,
         nullptr, 0, nullptr, BATCH * KVLEN, 1024, 1024, 1.f, 0, 1, 1);
    {
        dim3 grid(8, 64);
        flash_cross_kernel<<<grid, 256, CF_TOTAL * 4>>>(q, kv2, t);
    }
    gemm(t, 512, 0, 0, a2_o, 512, 0, 0, x, 512, 0, 0,
         x, 512, a2_ob, NTOK, 512, 512, 1.f, 0, 1, 1);

    // ---- feed-forward (GEGLU fused) ----
    layernorm_kernel<<<NTOK / 8, 256>>>(x, ln4_g, ln4_b, t, NTOK);
    gemm(t, 512, 0, 0, ff_proj_w, 4096, 0, 0, gl, 2048, 0, 0,
         nullptr, 0, ff_proj_b, NTOK, 2048, 512, 1.f, 0, 1, 1);
    gemm(t, 512, 0, 0, ff_proj_w + 2048, 4096, 0, 0, gl, 2048, 0, 0,
         gl, 2048, ff_proj_b + 2048, NTOK, 2048, 512, 1.f, 0, 1, 1, 1);
    gemm(gl, 2048, 0, 0, ff_out_w, 512, 0, 0, x, 512, 0, 0,
         x, 512, ff_out_b, NTOK, 512, 2048, 1.f, 0, 1, 1);

    // ---- output projection ----
    gemm(x, 512, 0, 0, fc_out_w, 512, 0, 0, t, 512, 0, 0,
         nullptr, 0, fc_out_b, NTOK, 512, 512, 1.f, 0, 1, 1);

    output_kernel<<<(BATCH * DIMC * SPATIAL) / 256, 256>>>(t, in_q, out);
}

// round 5
// speedup vs baseline: 5.3013x; 1.0310x over previous
#include <cuda_runtime.h>
#include <cstdint>
#include <math.h>

// ---------------------------------------------------------------------------
// Problem constants
// ---------------------------------------------------------------------------
#define BATCH   8
#define DIMC    512
#define SPATIAL 1024             // H*W = 32*32
#define NTOK    (BATCH*SPATIAL)  // 8192 tokens
#define HEADS   8
#define HDIM    64
#define KVLEN   77
#define KVDIM   1024

// ---------------------------------------------------------------------------
// Scratch buffers (static device globals: allocation-free)
// ---------------------------------------------------------------------------
__device__ float g_x   [(size_t)NTOK * DIMC];          // running activation
__device__ float g_t   [(size_t)NTOK * DIMC];          // temp / normalized
__device__ float g_q   [(size_t)NTOK * DIMC];          // cross-attn q
__device__ float g_qkv [(size_t)NTOK * 1536];          // packed self-attn q|k|v
__device__ float g_kv2 [(size_t)(BATCH*KVLEN) * 1024]; // packed cross k|v
__device__ float g_wq  [(size_t)512 * 1536];           // packed qkv weights
__device__ float g_wk2 [(size_t)1024 * 1024];          // packed cross kv weights
__device__ float g_gl  [(size_t)NTOK * 2048];          // geglu a-half / output

// ---------------------------------------------------------------------------
// Warp reduction helpers
// ---------------------------------------------------------------------------
__device__ __forceinline__ float warpSum(float v) {
    #pragma unroll
    for (int o = 16; o > 0; o >>= 1) v += __shfl_xor_sync(0xffffffffu, v, o);
    return v;
}

// ---------------------------------------------------------------------------
// mma / ldmatrix helpers (tf32, raw fp32 bits)
// ---------------------------------------------------------------------------
__device__ __forceinline__ void mma_tf32(float* d, const uint32_t* a, const uint32_t* b) {
    asm volatile(
        "mma.sync.aligned.m16n8k8.row.col.f32.tf32.tf32.f32 "
        "{%0,%1,%2,%3}, {%4,%5,%6,%7}, {%8,%9}, {%0,%1,%2,%3};"
        : "+f"(d[0]), "+f"(d[1]), "+f"(d[2]), "+f"(d[3])
        : "r"(a[0]), "r"(a[1]), "r"(a[2]), "r"(a[3]), "r"(b[0]), "r"(b[1]));
}
__device__ __forceinline__ void ldsm4(uint32_t& r0, uint32_t& r1,
                                      uint32_t& r2, uint32_t& r3, uint32_t addr) {
    asm volatile("ldmatrix.sync.aligned.m8n8.x4.shared.b16 {%0,%1,%2,%3}, [%4];"
                 : "=r"(r0), "=r"(r1), "=r"(r2), "=r"(r3) : "r"(addr));
}
__device__ __forceinline__ void cp_async16(uint32_t dst, const void* src, int bytes) {
    asm volatile("cp.async.cg.shared.global [%0], [%1], 16, %2;\n"
                 :: "r"(dst), "l"(src), "r"(bytes));
}
__device__ __forceinline__ void cp_commit() {
    asm volatile("cp.async.commit_group;\n");
}
__device__ __forceinline__ void cp_wait1() {
    asm volatile("cp.async.wait_group 1;\n");
}
__device__ __forceinline__ void cp_wait0() {
    asm volatile("cp.async.wait_group 0;\n");
}

// ---------------------------------------------------------------------------
// GroupNorm + transpose to token-major
// ---------------------------------------------------------------------------
__global__ void groupnorm_kernel(const float* __restrict__ qin,
                                 const float* __restrict__ gamma,
                                 const float* __restrict__ beta,
                                 float* __restrict__ out) {
    const int blk = blockIdx.x;
    const int b = blk >> 5;
    const int grp = blk & 31;
    const float* base = qin + ((size_t)b * DIMC + grp * 16) * SPATIAL;

    float s = 0.f, s2 = 0.f;
    for (int i = threadIdx.x; i < 16 * SPATIAL; i += 256) {
        float v = base[i];
        s += v; s2 += v * v;
    }
    __shared__ float red[2][8];
    s = warpSum(s); s2 = warpSum(s2);
    int wid = threadIdx.x >> 5, lid = threadIdx.x & 31;
    if (lid == 0) { red[0][wid] = s; red[1][wid] = s2; }
    __syncthreads();
    if (wid == 0) {
        float a = (lid < 8) ? red[0][lid] : 0.f;
        float c = (lid < 8) ? red[1][lid] : 0.f;
        a = warpSum(a); c = warpSum(c);
        if (lid == 0) { red[0][0] = a; red[1][0] = c; }
    }
    __syncthreads();
    const float mu  = red[0][0] * (1.f / 16384.f);
    const float var = red[1][0] * (1.f / 16384.f) - mu * mu;
    const float inv = rsqrtf(var + 1e-6f);

    for (int i = threadIdx.x; i < 16 * SPATIAL; i += 256) {
        int c = grp * 16 + (i >> 10);
        int sp = i & 1023;
        float v = (base[i] - mu) * inv * gamma[c] + beta[c];
        out[((size_t)(b * SPATIAL + sp)) * DIMC + c] = v;
    }
}

// ---------------------------------------------------------------------------
// LayerNorm over 512-dim rows. One warp per row.
// ---------------------------------------------------------------------------
__global__ void layernorm_kernel(const float* __restrict__ x,
                                 const float* __restrict__ gamma,
                                 const float* __restrict__ beta,
                                 float* __restrict__ out, int rows) {
    int row = blockIdx.x * 8 + (threadIdx.x >> 5);
    if (row >= rows) return;
    int lid = threadIdx.x & 31;
    const float4* xr = (const float4*)(x + (size_t)row * DIMC);

    float4 vals[4];
    float s = 0.f, s2 = 0.f;
    #pragma unroll
    for (int i = 0; i < 4; i++) {
        float4 v = xr[lid + 32 * i];
        vals[i] = v;
        s  += v.x + v.y + v.z + v.w;
        s2 += v.x*v.x + v.y*v.y + v.z*v.z + v.w*v.w;
    }
    s = warpSum(s); s2 = warpSum(s2);
    const float mu  = s * (1.f / 512.f);
    const float inv = rsqrtf(s2 * (1.f / 512.f) - mu * mu + 1e-5f);

    float4* orow = (float4*)(out + (size_t)row * DIMC);
    const float4* g4 = (const float4*)gamma;
    const float4* b4 = (const float4*)beta;
    #pragma unroll
    for (int i = 0; i < 4; i++) {
        int idx = lid + 32 * i;
        float4 v = vals[i], g = g4[idx], b = b4[idx], o;
        o.x = (v.x - mu) * inv * g.x + b.x;
        o.y = (v.y - mu) * inv * g.y + b.y;
        o.z = (v.z - mu) * inv * g.z + b.z;
        o.w = (v.w - mu) * inv * g.w + b.w;
        orow[idx] = o;
    }
}

// ---------------------------------------------------------------------------
// Weight packing
// ---------------------------------------------------------------------------
__global__ void pack3_kernel(const float* __restrict__ w0,
                             const float* __restrict__ w1,
                             const float* __restrict__ w2,
                             float* __restrict__ out) {
    int i = blockIdx.x * 256 + threadIdx.x;
    if (i >= 512 * 1536 / 4) return;
    int row = i / 384;
    int c4  = i % 384;
    const float4* src;
    int cc = c4;
    if (c4 < 128)       { src = (const float4*)w0; }
    else if (c4 < 256)  { src = (const float4*)w1; cc = c4 - 128; }
    else                { src = (const float4*)w2; cc = c4 - 256; }
    ((float4*)out)[i] = src[row * 128 + cc];
}

__global__ void pack2_kernel(const float* __restrict__ w0,
                             const float* __restrict__ w1,
                             float* __restrict__ out) {
    int i = blockIdx.x * 256 + threadIdx.x;
    if (i >= 1024 * 1024 / 4) return;
    int row = i / 256;
    int c4  = i % 256;
    const float4* src = c4 < 128 ? (const float4*)w0 : (const float4*)w1;
    int cc = c4 < 128 ? c4 : c4 - 128;
    ((float4*)out)[i] = src[row * 128 + cc];
}

// ---------------------------------------------------------------------------
// Final transpose + residual
// ---------------------------------------------------------------------------
__global__ void output_kernel(const float* __restrict__ t,
                              const float* __restrict__ qin,
                              float* __restrict__ out) {
    int i = blockIdx.x * 256 + threadIdx.x;
    if (i >= BATCH * DIMC * SPATIAL) return;
    int sp = i & 1023;
    int bc = i >> 10;
    int c = bc & 511;
    int b = bc >> 9;
    out[i] = t[((size_t)(b * SPATIAL + sp)) * DIMC + c] + qin[i];
}

// ===========================================================================
// Fused flash self-attention (ldmatrix fragment loads).
// ===========================================================================
#define FSTR 68
#define PSTR 132
#define FS_SQ   0
#define FS_SK   (128*FSTR)
#define FS_SVT  (FS_SK + 128*FSTR)
#define FS_SP   (FS_SVT + 64*PSTR)
#define FS_TOTAL (FS_SP + 128*PSTR)

__global__ void __launch_bounds__(256) flash_self_kernel(
    const float* __restrict__ qkv, float* __restrict__ outp) {
    extern __shared__ float sm[];
    float* sQ  = sm + FS_SQ;
    float* sK  = sm + FS_SK;
    float* sVt = sm + FS_SVT;
    float* sP  = sm + FS_SP;

    const int b  = blockIdx.y >> 3;
    const int h  = blockIdx.y & 7;
    const int q0 = blockIdx.x * 128;
    const int tid = threadIdx.x;
    const int warp = tid >> 5;
    const int lane = tid & 31;
    const int g  = lane >> 2;
    const int tg = lane & 3;
    const int wm = warp * 16;

    const uint32_t smb = (uint32_t)__cvta_generic_to_shared(sm);
    const uint32_t lmrow = (lane & 15);
    const uint32_t lmhi  = (lane >> 4) << 2;   // +4 k for upper matrices

    // ---- load Q tile, scaled by 1/8 ----
    for (int i = tid; i < 2048; i += 256) {
        int row = i >> 4;
        int c4  = (i & 15) * 4;
        const float4 v = *(const float4*)(qkv +
            (size_t)(b * 1024 + q0 + row) * 1536 + h * 64 + c4);
        float* d = sQ + row * FSTR + c4;
        d[0] = v.x * 0.125f; d[1] = v.y * 0.125f;
        d[2] = v.z * 0.125f; d[3] = v.w * 0.125f;
    }
    __syncthreads();

    // ---- cache Q fragments via ldmatrix ----
    uint32_t qf[8][4];
    {
        const uint32_t qbase = smb + (FS_SQ + (wm + lmrow) * FSTR + lmhi) * 4;
        #pragma unroll
        for (int kc = 0; kc < 8; kc++)
            ldsm4(qf[kc][0], qf[kc][1], qf[kc][2], qf[kc][3], qbase + kc * 32);
    }

    float m_[2] = {-1e30f, -1e30f};
    float l_[2] = {0.f, 0.f};
    float acco[8][4];
    #pragma unroll
    for (int i = 0; i < 8; i++)
        #pragma unroll
        for (int r = 0; r < 4; r++) acco[i][r] = 0.f;

    const uint32_t kbase = smb + (FS_SK + lmrow * FSTR + lmhi) * 4;
    const uint32_t pbase = smb + (FS_SP + (wm + lmrow) * PSTR + lmhi) * 4;
    const uint32_t vbase = smb + (FS_SVT + lmrow * PSTR + lmhi) * 4;

    for (int j = 0; j < 8; j++) {
        // ---- load K tile + V tile (transposed) ----
        for (int i = tid; i < 2048; i += 256) {
            int row = i >> 4;
            int c4  = (i & 15) * 4;
            const float* base = qkv + (size_t)(b * 1024 + j * 128 + row) * 1536 + h * 64;
            const float4 kv4 = *(const float4*)(base + 512 + c4);
            float* dk = sK + row * FSTR + c4;
            dk[0] = kv4.x; dk[1] = kv4.y; dk[2] = kv4.z; dk[3] = kv4.w;
            const float4 vv = *(const float4*)(base + 1024 + c4);
            sVt[(c4 + 0) * PSTR + row] = vv.x;
            sVt[(c4 + 1) * PSTR + row] = vv.y;
            sVt[(c4 + 2) * PSTR + row] = vv.z;
            sVt[(c4 + 3) * PSTR + row] = vv.w;
        }
        __syncthreads();

        // ---- S = Q @ K^T (16 x 128 per warp) ----
        float accs[16][4];
        #pragma unroll
        for (int nt = 0; nt < 16; nt++)
            #pragma unroll
            for (int r = 0; r < 4; r++) accs[nt][r] = 0.f;

        #pragma unroll
        for (int kc = 0; kc < 8; kc++) {
            const uint32_t ka = kbase + kc * 32;
            #pragma unroll
            for (int p = 0; p < 8; p++) {
                uint32_t b0, b1, b2, b3;
                ldsm4(b0, b1, b2, b3, ka + (uint32_t)(p * 16 * FSTR) * 4);
                uint32_t bf0[2] = {b0, b2};
                uint32_t bf1[2] = {b1, b3};
                mma_tf32(accs[2 * p],     qf[kc], bf0);
                mma_tf32(accs[2 * p + 1], qf[kc], bf1);
            }
        }

        // ---- online softmax update ----
        float mx0 = -1e30f, mx1 = -1e30f;
        #pragma unroll
        for (int nt = 0; nt < 16; nt++) {
            mx0 = fmaxf(mx0, fmaxf(accs[nt][0], accs[nt][1]));
            mx1 = fmaxf(mx1, fmaxf(accs[nt][2], accs[nt][3]));
        }
        mx0 = fmaxf(mx0, __shfl_xor_sync(0xffffffffu, mx0, 1));
        mx0 = fmaxf(mx0, __shfl_xor_sync(0xffffffffu, mx0, 2));
        mx1 = fmaxf(mx1, __shfl_xor_sync(0xffffffffu, mx1, 1));
        mx1 = fmaxf(mx1, __shfl_xor_sync(0xffffffffu, mx1, 2));
        const float mn0 = fmaxf(m_[0], mx0);
        const float mn1 = fmaxf(m_[1], mx1);
        const float c0 = __expf(m_[0] - mn0);
        const float c1 = __expf(m_[1] - mn1);
        l_[0] *= c0; l_[1] *= c1;
        #pragma unroll
        for (int nt = 0; nt < 8; nt++) {
            acco[nt][0] *= c0; acco[nt][1] *= c0;
            acco[nt][2] *= c1; acco[nt][3] *= c1;
        }
        float rs0 = 0.f, rs1 = 0.f;
        float* p0 = sP + (wm + g) * PSTR + 2 * tg;
        float* p1 = sP + (wm + g + 8) * PSTR + 2 * tg;
        #pragma unroll
        for (int nt = 0; nt < 16; nt++) {
            const float e0 = __expf(accs[nt][0] - mn0);
            const float e1 = __expf(accs[nt][1] - mn0);
            const float e2 = __expf(accs[nt][2] - mn1);
            const float e3 = __expf(accs[nt][3] - mn1);
            rs0 += e0 + e1; rs1 += e2 + e3;
            p0[nt * 8 + 0] = e0; p0[nt * 8 + 1] = e1;
            p1[nt * 8 + 0] = e2; p1[nt * 8 + 1] = e3;
        }
        rs0 += __shfl_xor_sync(0xffffffffu, rs0, 1);
        rs0 += __shfl_xor_sync(0xffffffffu, rs0, 2);
        rs1 += __shfl_xor_sync(0xffffffffu, rs1, 1);
        rs1 += __shfl_xor_sync(0xffffffffu, rs1, 2);
        l_[0] += rs0; l_[1] += rs1;
        m_[0] = mn0; m_[1] = mn1;
        __syncwarp();

        // ---- O += P @ V  (K dim = 128) ----
        #pragma unroll
        for (int kc = 0; kc < 16; kc++) {
            uint32_t af[4];
            ldsm4(af[0], af[1], af[2], af[3], pbase + kc * 32);
            const uint32_t va = vbase + kc * 32;
            #pragma unroll
            for (int p = 0; p < 4; p++) {
                uint32_t b0, b1, b2, b3;
                ldsm4(b0, b1, b2, b3, va + (uint32_t)(p * 16 * PSTR) * 4);
                uint32_t bf0[2] = {b0, b2};
                uint32_t bf1[2] = {b1, b3};
                mma_tf32(acco[2 * p],     af, bf0);
                mma_tf32(acco[2 * p + 1], af, bf1);
            }
        }
        __syncthreads();   // before overwriting sK/sVt next iter
    }

    // ---- epilogue ----
    const float i0 = 1.f / l_[0];
    const float i1 = 1.f / l_[1];
    const int row0 = b * 1024 + q0 + wm + g;
    #pragma unroll
    for (int nt = 0; nt < 8; nt++) {
        const int col = h * 64 + nt * 8 + 2 * tg;
        outp[(size_t)row0 * 512 + col]           = acco[nt][0] * i0;
        outp[(size_t)row0 * 512 + col + 1]       = acco[nt][1] * i0;
        outp[(size_t)(row0 + 8) * 512 + col]     = acco[nt][2] * i1;
        outp[(size_t)(row0 + 8) * 512 + col + 1] = acco[nt][3] * i1;
    }
}

// ===========================================================================
// Fused flash cross-attention (kv len 77, padded to 80, single tile).
// ===========================================================================
#define CSTR 84
#define CF_SQ   0
#define CF_SK   (128*FSTR)
#define CF_SVT  (CF_SK + 80*FSTR)
#define CF_SP   (CF_SVT + 64*CSTR)
#define CF_TOTAL (CF_SP + 128*CSTR)

__global__ void __launch_bounds__(256) flash_cross_kernel(
    const float* __restrict__ qsrc, const float* __restrict__ kv2,
    float* __restrict__ outp) {
    extern __shared__ float sm[];
    float* sQ  = sm + CF_SQ;
    float* sK  = sm + CF_SK;
    float* sVt = sm + CF_SVT;
    float* sP  = sm + CF_SP;

    const int b  = blockIdx.y >> 3;
    const int h  = blockIdx.y & 7;
    const int q0 = blockIdx.x * 128;
    const int tid = threadIdx.x;
    const int warp = tid >> 5;
    const int lane = tid & 31;
    const int g  = lane >> 2;
    const int tg = lane & 3;
    const int wm = warp * 16;

    const uint32_t smb = (uint32_t)__cvta_generic_to_shared(sm);
    const uint32_t lmrow = (lane & 15);
    const uint32_t lmhi  = (lane >> 4) << 2;

    // ---- load Q (scaled) ----
    for (int i = tid; i < 2048; i += 256) {
        int row = i >> 4;
        int c4  = (i & 15) * 4;
        const float4 v = *(const float4*)(qsrc +
            (size_t)(b * 1024 + q0 + row) * 512 + h * 64 + c4);
        float* d = sQ + row * FSTR + c4;
        d[0] = v.x * 0.125f; d[1] = v.y * 0.125f;
        d[2] = v.z * 0.125f; d[3] = v.w * 0.125f;
    }
    // ---- load K (80 rows, pad zero) + V transposed ----
    for (int i = tid; i < 1280; i += 256) {
        int row = i >> 4;
        int c4  = (i & 15) * 4;
        float4 kk = make_float4(0.f, 0.f, 0.f, 0.f);
        float4 vv = make_float4(0.f, 0.f, 0.f, 0.f);
        if (row < KVLEN) {
            const float* base = kv2 + (size_t)(b * KVLEN + row) * 1024 + h * 64;
            kk = *(const float4*)(base + c4);
            vv = *(const float4*)(base + 512 + c4);
        }
        float* dk = sK + row * FSTR + c4;
        dk[0] = kk.x; dk[1] = kk.y; dk[2] = kk.z; dk[3] = kk.w;
        sVt[(c4 + 0) * CSTR + row] = vv.x;
        sVt[(c4 + 1) * CSTR + row] = vv.y;
        sVt[(c4 + 2) * CSTR + row] = vv.z;
        sVt[(c4 + 3) * CSTR + row] = vv.w;
    }
    __syncthreads();

    // ---- Q fragments ----
    uint32_t qf[8][4];
    {
        const uint32_t qbase = smb + (CF_SQ + (wm + lmrow) * FSTR + lmhi) * 4;
        #pragma unroll
        for (int kc = 0; kc < 8; kc++)
            ldsm4(qf[kc][0], qf[kc][1], qf[kc][2], qf[kc][3], qbase + kc * 32);
    }

    // ---- S = Q @ K^T  (16 x 80 per warp) ----
    float accs[10][4];
    #pragma unroll
    for (int nt = 0; nt < 10; nt++)
        #pragma unroll
        for (int r = 0; r < 4; r++) accs[nt][r] = 0.f;
    {
        const uint32_t kbase = smb + (CF_SK + lmrow * FSTR + lmhi) * 4;
        #pragma unroll
        for (int kc = 0; kc < 8; kc++) {
            const uint32_t ka = kbase + kc * 32;
            #pragma unroll
            for (int p = 0; p < 5; p++) {
                uint32_t b0, b1, b2, b3;
                ldsm4(b0, b1, b2, b3, ka + (uint32_t)(p * 16 * FSTR) * 4);
                uint32_t bf0[2] = {b0, b2};
                uint32_t bf1[2] = {b1, b3};
                mma_tf32(accs[2 * p],     qf[kc], bf0);
                mma_tf32(accs[2 * p + 1], qf[kc], bf1);
            }
        }
    }

    // ---- mask cols >= 77, softmax ----
    #pragma unroll
    for (int nt = 0; nt < 10; nt++) {
        const int col0 = nt * 8 + 2 * tg;
        if (col0 >= KVLEN)     { accs[nt][0] = -1e30f; accs[nt][2] = -1e30f; }
        if (col0 + 1 >= KVLEN) { accs[nt][1] = -1e30f; accs[nt][3] = -1e30f; }
    }
    float mx0 = -1e30f, mx1 = -1e30f;
    #pragma unroll
    for (int nt = 0; nt < 10; nt++) {
        mx0 = fmaxf(mx0, fmaxf(accs[nt][0], accs[nt][1]));
        mx1 = fmaxf(mx1, fmaxf(accs[nt][2], accs[nt][3]));
    }
    mx0 = fmaxf(mx0, __shfl_xor_sync(0xffffffffu, mx0, 1));
    mx0 = fmaxf(mx0, __shfl_xor_sync(0xffffffffu, mx0, 2));
    mx1 = fmaxf(mx1, __shfl_xor_sync(0xffffffffu, mx1, 1));
    mx1 = fmaxf(mx1, __shfl_xor_sync(0xffffffffu, mx1, 2));

    float rs0 = 0.f, rs1 = 0.f;
    float* p0 = sP + (wm + g) * CSTR + 2 * tg;
    float* p1 = sP + (wm + g + 8) * CSTR + 2 * tg;
    #pragma unroll
    for (int nt = 0; nt < 10; nt++) {
        const float e0 = __expf(accs[nt][0] - mx0);
        const float e1 = __expf(accs[nt][1] - mx0);
        const float e2 = __expf(accs[nt][2] - mx1);
        const float e3 = __expf(accs[nt][3] - mx1);
        rs0 += e0 + e1; rs1 += e2 + e3;
        p0[nt * 8 + 0] = e0; p0[nt * 8 + 1] = e1;
        p1[nt * 8 + 0] = e2; p1[nt * 8 + 1] = e3;
    }
    rs0 += __shfl_xor_sync(0xffffffffu, rs0, 1);
    rs0 += __shfl_xor_sync(0xffffffffu, rs0, 2);
    rs1 += __shfl_xor_sync(0xffffffffu, rs1, 1);
    rs1 += __shfl_xor_sync(0xffffffffu, rs1, 2);
    __syncwarp();

    // ---- O = P @ V  (K dim = 80) ----
    float acco[8][4];
    #pragma unroll
    for (int nt = 0; nt < 8; nt++)
        #pragma unroll
        for (int r = 0; r < 4; r++) acco[nt][r] = 0.f;
    {
        const uint32_t pb = smb + (CF_SP + (wm + lmrow) * CSTR + lmhi) * 4;
        const uint32_t vb = smb + (CF_SVT + lmrow * CSTR + lmhi) * 4;
        #pragma unroll
        for (int kc = 0; kc < 10; kc++) {
            uint32_t af[4];
            ldsm4(af[0], af[1], af[2], af[3], pb + kc * 32);
            const uint32_t va = vb + kc * 32;
            #pragma unroll
            for (int p = 0; p < 4; p++) {
                uint32_t b0, b1, b2, b3;
                ldsm4(b0, b1, b2, b3, va + (uint32_t)(p * 16 * CSTR) * 4);
                uint32_t bf0[2] = {b0, b2};
                uint32_t bf1[2] = {b1, b3};
                mma_tf32(acco[2 * p],     af, bf0);
                mma_tf32(acco[2 * p + 1], af, bf1);
            }
        }
    }

    const float i0 = 1.f / rs0;
    const float i1 = 1.f / rs1;
    const int row0 = b * 1024 + q0 + wm + g;
    #pragma unroll
    for (int nt = 0; nt < 8; nt++) {
        const int col = h * 64 + nt * 8 + 2 * tg;
        outp[(size_t)row0 * 512 + col]           = acco[nt][0] * i0;
        outp[(size_t)row0 * 512 + col + 1]       = acco[nt][1] * i0;
        outp[(size_t)(row0 + 8) * 512 + col]     = acco[nt][2] * i1;
        outp[(size_t)(row0 + 8) * 512 + col + 1] = acco[nt][3] * i1;
    }
}

// ===========================================================================
// TF32 tensor-core GEMM, specialized: C = A@B (+bias)(+Res / GEGLU)
//   A [M,K] row-major, B [K,N] row-major. N % 128 == 0, K % 32 == 0.
//   Only M may be ragged (kv2: 616). 3-stage cp.async, 1 barrier/tile,
//   ldmatrix A-fragments.
// ===========================================================================
#define BM 128
#define BN 128
#define BK 32
#define ASTRIDE 36
#define BSTRIDE 136
#define STG_A (128*ASTRIDE)              // 4608
#define STG_FLOATS (STG_A + 32*BSTRIDE)  // 8960
#define NSTAGE 3
#define GEMM_SMEM (NSTAGE * STG_FLOATS * 4)   // 107520 B

__global__ void __launch_bounds__(256) gemm_tf32_kernel(
    const float* __restrict__ A, int lda,
    const float* __restrict__ B, int ldb,
    float* __restrict__ C, int ldc,
    const float* __restrict__ Res, int ldres,
    const float* __restrict__ bias,
    int M, int N, int K, int emode) {

    extern __shared__ float smem[];

    const int m0 = blockIdx.y * BM;
    const int n0 = blockIdx.x * BN;
    const int tid = threadIdx.x;
    const int warp = tid >> 5;
    const int lane = tid & 31;
    const int g  = lane >> 2;
    const int tg = lane & 3;
    const int wm = (warp >> 2) * 64;
    const int wn = (warp & 3) * 32;

    const uint32_t smem_u32 = (uint32_t)__cvta_generic_to_shared(smem);
    const int nk = K / BK;

    float acc[4][4][4];
    #pragma unroll
    for (int i = 0; i < 4; i++)
        #pragma unroll
        for (int j = 0; j < 4; j++)
            #pragma unroll
            for (int r = 0; r < 4; r++) acc[i][j][r] = 0.f;

    // per-thread load coordinates
    const int a_row = tid >> 1;            // 0..127 (2 chunks per row)
    const int a_kc  = (tid & 1) * 16;      // handled as 2 rows of 4 chunks? see below
    (void)a_row; (void)a_kc;

    auto load_stage = [&](int stage, int k0) {
        const uint32_t abase = smem_u32 + (uint32_t)(stage * STG_FLOATS) * 4;
        // A: 128 rows x 32 floats = 1024 16B-chunks, 4 per thread
        #pragma unroll
        for (int i = 0; i < 4; i++) {
            int idx = tid + i * 256;
            int row = idx >> 3;
            int kc  = (idx & 7) * 4;
            int bytes = (m0 + row < M) ? 16 : 0;
            cp_async16(abase + (uint32_t)(row * ASTRIDE + kc) * 4,
                       A + (long long)(m0 + row) * lda + k0 + kc, bytes);
        }
        const uint32_t bbase = abase + (uint32_t)STG_A * 4;
        // B: 32 k-rows x 128 floats = 1024 chunks, 4 per thread (N,K in-bounds)
        #pragma unroll
        for (int i = 0; i < 4; i++) {
            int idx = tid + i * 256;
            int k  = idx >> 5;
            int nc = (idx & 31) * 4;
            cp_async16(bbase + (uint32_t)(k * BSTRIDE + nc) * 4,
                       B + (long long)(k0 + k) * ldb + n0 + nc, 16);
        }
        cp_commit();
    };

    const uint32_t a_lm = smem_u32 +
        (uint32_t)((wm + (lane & 15)) * ASTRIDE + ((lane >> 4) << 2)) * 4;

    auto compute_stage = [&](int stage) {
        const uint32_t abase = a_lm + (uint32_t)(stage * STG_FLOATS) * 4;
        const uint32_t* Bs = (const uint32_t*)(smem + stage * STG_FLOATS + STG_A);
        #pragma unroll
        for (int ks = 0; ks < 4; ks++) {
            const int kk = ks * 8;
            uint32_t afr[4][4];
            #pragma unroll
            for (int mt = 0; mt < 4; mt++)
                ldsm4(afr[mt][0], afr[mt][1], afr[mt][2], afr[mt][3],
                      abase + (uint32_t)(mt * 16 * ASTRIDE + kk) * 4);
            uint32_t bfr[4][2];
            #pragma unroll
            for (int nt = 0; nt < 4; nt++) {
                const int nb = wn + nt * 8;
                bfr[nt][0] = Bs[(kk + tg)     * BSTRIDE + nb + g];
                bfr[nt][1] = Bs[(kk + tg + 4) * BSTRIDE + nb + g];
            }
            #pragma unroll
            for (int mt = 0; mt < 4; mt++)
                #pragma unroll
                for (int nt = 0; nt < 4; nt++)
                    mma_tf32(acc[mt][nt], afr[mt], bfr[nt]);
        }
    };

    load_stage(0, 0);
    load_stage(1, BK);
    int scur = 0, sload = 2;
    for (int kt = 0; kt < nk; kt++) {
        if (kt + 1 < nk) cp_wait1(); else cp_wait0();
        __syncthreads();
        if (kt + 2 < nk) {
            load_stage(sload, (kt + 2) * BK);
            sload = (sload == 2) ? 0 : sload + 1;
        }
        compute_stage(scur);
        scur = (scur == 2) ? 0 : scur + 1;
    }

    // ---- epilogue ----
    #pragma unroll
    for (int mt = 0; mt < 4; mt++) {
        #pragma unroll
        for (int nt = 0; nt < 4; nt++) {
            const int row0 = m0 + wm + mt * 16 + g;
            const int col0 = n0 + wn + nt * 8 + tg * 2;
            #pragma unroll
            for (int r = 0; r < 4; r++) {
                const int row = row0 + (r >> 1) * 8;
                const int col = col0 + (r & 1);
                if (row < M) {
                    float v = acc[mt][nt][r];
                    if (bias) v += bias[col];
                    if (emode == 1) {
                        float ge = 0.5f * v * (1.f + erff(v * 0.70710678118654752f));
                        v = Res[(long long)row * ldres + col] * ge;
                    } else if (Res) {
                        v += Res[(long long)row * ldres + col];
                    }
                    C[(long long)row * ldc + col] = v;
                }
            }
        }
    }
}

// ---------------------------------------------------------------------------
// Host side
// ---------------------------------------------------------------------------
static void gemm(const float* A, int lda, const float* B, int ldb,
                 float* C, int ldc, const float* Res, int ldres,
                 const float* bias, int M, int N, int K, int emode = 0) {
    dim3 grid(N / BN, (M + BM - 1) / BM);
    gemm_tf32_kernel<<<grid, 256, GEMM_SMEM>>>(
        A, lda, B, ldb, C, ldc, Res, ldres, bias, M, N, K, emode);
}

extern "C" void kernel_launch(void* const* d_in, const int* in_sizes, int n_in,
                              void* d_out, int out_size) {
    const float* in_q     = (const float*)d_in[0];
    const float* in_kv    = (const float*)d_in[1];
    const float* gn_g     = (const float*)d_in[2];
    const float* gn_b     = (const float*)d_in[3];
    const float* ln2_g    = (const float*)d_in[4];
    const float* ln2_b    = (const float*)d_in[5];
    const float* ln3_g    = (const float*)d_in[6];
    const float* ln3_b    = (const float*)d_in[7];
    const float* ln4_g    = (const float*)d_in[8];
    const float* ln4_b    = (const float*)d_in[9];
    const float* fc_in_w  = (const float*)d_in[10];
    const float* fc_in_b  = (const float*)d_in[11];
    const float* fc_out_w = (const float*)d_in[12];
    const float* fc_out_b = (const float*)d_in[13];
    const float* a1_q     = (const float*)d_in[14];
    const float* a1_k     = (const float*)d_in[15];
    const float* a1_v     = (const float*)d_in[16];
    const float* a1_o     = (const float*)d_in[17];
    const float* a1_ob    = (const float*)d_in[18];
    const float* a2_q     = (const float*)d_in[19];
    const float* a2_k     = (const float*)d_in[20];
    const float* a2_v     = (const float*)d_in[21];
    const float* a2_o     = (const float*)d_in[22];
    const float* a2_ob    = (const float*)d_in[23];
    const float* ff_proj_w = (const float*)d_in[24];
    const float* ff_proj_b = (const float*)d_in[25];
    const float* ff_out_w  = (const float*)d_in[26];
    const float* ff_out_b  = (const float*)d_in[27];

    cudaFuncSetAttribute(gemm_tf32_kernel,
                         cudaFuncAttributeMaxDynamicSharedMemorySize, GEMM_SMEM);
    cudaFuncSetAttribute(flash_self_kernel,
                         cudaFuncAttributeMaxDynamicSharedMemorySize, FS_TOTAL * 4);
    cudaFuncSetAttribute(flash_cross_kernel,
                         cudaFuncAttributeMaxDynamicSharedMemorySize, CF_TOTAL * 4);

    float *x, *t, *q, *qkv, *kv2, *wq, *wk2, *gl;
    cudaGetSymbolAddress((void**)&x,   g_x);
    cudaGetSymbolAddress((void**)&t,   g_t);
    cudaGetSymbolAddress((void**)&q,   g_q);
    cudaGetSymbolAddress((void**)&qkv, g_qkv);
    cudaGetSymbolAddress((void**)&kv2, g_kv2);
    cudaGetSymbolAddress((void**)&wq,  g_wq);
    cudaGetSymbolAddress((void**)&wk2, g_wk2);
    cudaGetSymbolAddress((void**)&gl,  g_gl);

    float* out = (float*)d_out;

    // weight packing
    pack3_kernel<<<(512 * 1536 / 4 + 255) / 256, 256>>>(a1_q, a1_k, a1_v, wq);
    pack2_kernel<<<(1024 * 1024 / 4 + 255) / 256, 256>>>(a2_k, a2_v, wk2);

    // 1. GroupNorm + transpose to tokens -> t
    groupnorm_kernel<<<BATCH * 32, 256>>>(in_q, gn_g, gn_b, t);

    // 2. x = t @ fc_in_w + fc_in_b
    gemm(t, 512, fc_in_w, 512, x, 512, nullptr, 0, fc_in_b, NTOK, 512, 512);

    // ---- self attention ----
    layernorm_kernel<<<NTOK / 8, 256>>>(x, ln2_g, ln2_b, t, NTOK);
    gemm(t, 512, wq, 1536, qkv, 1536, nullptr, 0, nullptr, NTOK, 1536, 512);
    {
        dim3 grid(8, 64);
        flash_self_kernel<<<grid, 256, FS_TOTAL * 4>>>(qkv, t);
    }
    gemm(t, 512, a1_o, 512, x, 512, x, 512, a1_ob, NTOK, 512, 512);

    // ---- cross attention ----
    layernorm_kernel<<<NTOK / 8, 256>>>(x, ln3_g, ln3_b, t, NTOK);
    gemm(t, 512, a2_q, 512, q, 512, nullptr, 0, nullptr, NTOK, 512, 512);
    gemm(in_kv, 1024, wk2, 1024, kv2, 1024, nullptr, 0, nullptr,
         BATCH * KVLEN, 1024, 1024);
    {
        dim3 grid(8, 64);
        flash_cross_kernel<<<grid, 256, CF_TOTAL * 4>>>(q, kv2, t);
    }
    gemm(t, 512, a2_o, 512, x, 512, x, 512, a2_ob, NTOK, 512, 512);

    // ---- feed-forward (GEGLU fused) ----
    layernorm_kernel<<<NTOK / 8, 256>>>(x, ln4_g, ln4_b, t, NTOK);
    gemm(t, 512, ff_proj_w, 4096, gl, 2048, nullptr, 0, ff_proj_b,
         NTOK, 2048, 512);
    gemm(t, 512, ff_proj_w + 2048, 4096, gl, 2048, gl, 2048,
         ff_proj_b + 2048, NTOK, 2048, 512, 1);
    gemm(gl, 2048, ff_out_w, 512, x, 512, x, 512, ff_out_b, NTOK, 512, 2048);

    // ---- output projection ----
    gemm(x, 512, fc_out_w, 512, t, 512, nullptr, 0, fc_out_b, NTOK, 512, 512);

    output_kernel<<<(BATCH * DIMC * SPATIAL) / 256, 256>>>(t, in_q, out);
}